// round 1
// baseline (speedup 1.0000x reference)
#include <cuda_runtime.h>
#include <cuda_bf16.h>
#include <math.h>

// Problem constants
#define B_SZ 2
#define S_LEN 2048
#define E_DIM 1024
#define H_NUM 16
#define D_HEAD 64
#define M_ROWS (B_SZ * S_LEN)        // 4096
#define ATTN_SCALE 0.03125f          // 1/sqrt(1024)

// ---------------- scratch (device globals: no allocation allowed) ----------
__device__ float g_q[M_ROWS * E_DIM];
__device__ float g_k[M_ROWS * E_DIM];
__device__ float g_v[M_ROWS * E_DIM];
__device__ float g_a[M_ROWS * E_DIM];

// ---------------------------------------------------------------------------
// GEMM: Y[M][N] = X[M][K] * W[N][K]^T   with M=4096, N=1024, K=1024
// 64x64 output tile, BK=16, 256 threads, 4x4 register micro-tile.
// ---------------------------------------------------------------------------
__global__ __launch_bounds__(256) void gemm_xwT(const float* __restrict__ X,
                                                const float* __restrict__ W,
                                                float* __restrict__ Y) {
    const int K = E_DIM;
    const int N = E_DIM;
    __shared__ float Xs[16][64];
    __shared__ float Ws[16][64];

    int tid = threadIdx.x;
    int ty = tid >> 4;          // 0..15
    int tx = tid & 15;          // 0..15
    int mb = blockIdx.y * 64;
    int nb = blockIdx.x * 64;

    int lr  = tid >> 2;         // 0..63  (row within tile for loads)
    int lc4 = (tid & 3) * 4;    // 0,4,8,12 (k offset for loads)

    float acc[4][4];
#pragma unroll
    for (int i = 0; i < 4; i++)
#pragma unroll
        for (int j = 0; j < 4; j++) acc[i][j] = 0.f;

    for (int k0 = 0; k0 < K; k0 += 16) {
        float4 xv = *(const float4*)&X[(size_t)(mb + lr) * K + k0 + lc4];
        float4 wv = *(const float4*)&W[(size_t)(nb + lr) * K + k0 + lc4];
        Xs[lc4 + 0][lr] = xv.x; Xs[lc4 + 1][lr] = xv.y;
        Xs[lc4 + 2][lr] = xv.z; Xs[lc4 + 3][lr] = xv.w;
        Ws[lc4 + 0][lr] = wv.x; Ws[lc4 + 1][lr] = wv.y;
        Ws[lc4 + 2][lr] = wv.z; Ws[lc4 + 3][lr] = wv.w;
        __syncthreads();

#pragma unroll
        for (int kk = 0; kk < 16; kk++) {
            float4 a = *(const float4*)&Xs[kk][ty * 4];
            float4 b = *(const float4*)&Ws[kk][tx * 4];
            acc[0][0] += a.x * b.x; acc[0][1] += a.x * b.y;
            acc[0][2] += a.x * b.z; acc[0][3] += a.x * b.w;
            acc[1][0] += a.y * b.x; acc[1][1] += a.y * b.y;
            acc[1][2] += a.y * b.z; acc[1][3] += a.y * b.w;
            acc[2][0] += a.z * b.x; acc[2][1] += a.z * b.y;
            acc[2][2] += a.z * b.z; acc[2][3] += a.z * b.w;
            acc[3][0] += a.w * b.x; acc[3][1] += a.w * b.y;
            acc[3][2] += a.w * b.z; acc[3][3] += a.w * b.w;
        }
        __syncthreads();
    }

#pragma unroll
    for (int i = 0; i < 4; i++) {
        float4 o = make_float4(acc[i][0], acc[i][1], acc[i][2], acc[i][3]);
        *(float4*)&Y[(size_t)(mb + ty * 4 + i) * N + nb + tx * 4] = o;
    }
}

// ---------------------------------------------------------------------------
// RoPE applied in-place to q and k.  Layout: [b][s][h][d], pair (2i, 2i+1).
// Double-precision trig to keep angle error well under the 1e-3 budget.
// ---------------------------------------------------------------------------
__global__ __launch_bounds__(256) void rope_kernel(float* __restrict__ q,
                                                   float* __restrict__ k) {
    int p = blockIdx.x * blockDim.x + threadIdx.x;   // B*S*H*32 = 2,097,152
    int i = p & 31;
    int h = (p >> 5) & 15;
    int s = (p >> 9) & 2047;
    int b = p >> 20;
    size_t off = ((size_t)(b * S_LEN + s) * E_DIM + h * D_HEAD + 2 * i);

    double inv = exp(-((double)(2 * i) / 64.0) * log(10000.0));
    double ang = (double)s * inv;
    double cd, sd;
    sincos(ang, &sd, &cd);
    float c = (float)cd, sn = (float)sd;

    float x1 = q[off], x2 = q[off + 1];
    q[off]     = x1 * c - x2 * sn;
    q[off + 1] = x2 * c + x1 * sn;
    x1 = k[off]; x2 = k[off + 1];
    k[off]     = x1 * c - x2 * sn;
    k[off + 1] = x2 * c + x1 * sn;
}

// ---------------------------------------------------------------------------
// Causal flash attention.  One block = 64 query rows of one (b,h).
// 256 threads: thread quad (4 lanes) owns one query row.
// smem tiles padded to ld=66 for conflict-free float2 patterns.
// ---------------------------------------------------------------------------
#define LDP 66
#define SMEM_ATTN (4 * 64 * LDP * 4)

__global__ __launch_bounds__(256) void attn_kernel(const float* __restrict__ q,
                                                   const float* __restrict__ k,
                                                   const float* __restrict__ v,
                                                   float* __restrict__ o) {
    extern __shared__ float sm[];
    float* Qs = sm;                  // 64 x LDP
    float* Ks = Qs + 64 * LDP;
    float* Vs = Ks + 64 * LDP;
    float* Ps = Vs + 64 * LDP;

    int tid = threadIdx.x;
    int bh = blockIdx.y;
    int b = bh >> 4;
    int h = bh & 15;
    int qbase = blockIdx.x * 64;

    // base offset helper: element (s, d) of this (b,h)
    // addr = ((b*S + s)*E + h*64 + d)
    const size_t bh_off = (size_t)b * S_LEN * E_DIM + (size_t)h * D_HEAD;

    // load Q tile (float2 coalesced)
    for (int idx = tid; idx < 64 * 32; idx += 256) {
        int rr = idx >> 5;
        int d2 = idx & 31;
        float2 val = *(const float2*)&q[bh_off + (size_t)(qbase + rr) * E_DIM + 2 * d2];
        Qs[rr * LDP + 2 * d2]     = val.x;
        Qs[rr * LDP + 2 * d2 + 1] = val.y;
    }

    int r = tid >> 2;        // query row within tile
    int lane4 = tid & 3;

    float m_r = -INFINITY;
    float l_r = 0.f;
    float Oacc[16];
#pragma unroll
    for (int j = 0; j < 16; j++) Oacc[j] = 0.f;

    int grow = qbase + r;
    int ktiles = blockIdx.x + 1;

    for (int kt = 0; kt < ktiles; kt++) {
        int kbase = kt * 64;
        __syncthreads();   // previous iteration's reads of Ks/Vs done
        for (int idx = tid; idx < 64 * 32; idx += 256) {
            int rr = idx >> 5;
            int d2 = idx & 31;
            size_t gofs = bh_off + (size_t)(kbase + rr) * E_DIM + 2 * d2;
            float2 kv = *(const float2*)&k[gofs];
            float2 vv = *(const float2*)&v[gofs];
            Ks[rr * LDP + 2 * d2]     = kv.x;
            Ks[rr * LDP + 2 * d2 + 1] = kv.y;
            Vs[rr * LDP + 2 * d2]     = vv.x;
            Vs[rr * LDP + 2 * d2 + 1] = vv.y;
        }
        __syncthreads();

        // ---- scores: 16 columns per thread (c = lane4 + 4*j) ----
        float acc[16];
#pragma unroll
        for (int j = 0; j < 16; j++) acc[j] = 0.f;

        for (int d2 = 0; d2 < 32; d2++) {
            float2 qv = *(const float2*)&Qs[r * LDP + 2 * d2];
#pragma unroll
            for (int j = 0; j < 16; j++) {
                int c = lane4 + 4 * j;
                float2 kv = *(const float2*)&Ks[c * LDP + 2 * d2];
                acc[j] += qv.x * kv.x + qv.y * kv.y;
            }
        }

        bool diag = (kt == blockIdx.x);
        float tmax = -INFINITY;
#pragma unroll
        for (int j = 0; j < 16; j++) {
            float sc = acc[j] * ATTN_SCALE;
            if (diag && (kbase + lane4 + 4 * j) > grow) sc = -INFINITY;
            acc[j] = sc;
            tmax = fmaxf(tmax, sc);
        }
        // quad reduce (4 consecutive lanes share a row)
        tmax = fmaxf(tmax, __shfl_xor_sync(0xFFFFFFFF, tmax, 1));
        tmax = fmaxf(tmax, __shfl_xor_sync(0xFFFFFFFF, tmax, 2));

        float m_new = fmaxf(m_r, tmax);
        float alpha = __expf(m_r - m_new);

        float psum = 0.f;
#pragma unroll
        for (int j = 0; j < 16; j++) {
            float pv = __expf(acc[j] - m_new);   // exp(-inf) = 0 handles mask
            Ps[r * LDP + lane4 + 4 * j] = pv;
            psum += pv;
        }
        psum += __shfl_xor_sync(0xFFFFFFFF, psum, 1);
        psum += __shfl_xor_sync(0xFFFFFFFF, psum, 2);

        l_r = l_r * alpha + psum;
        m_r = m_new;
#pragma unroll
        for (int j = 0; j < 16; j++) Oacc[j] *= alpha;

        __syncthreads();   // Ps visible to whole quad (and block)

        // ---- O += P * V : thread owns dims od = lane4*2 + 8*jj (+1) ----
        for (int kk = 0; kk < 64; kk++) {
            float pv = Ps[r * LDP + kk];
#pragma unroll
            for (int jj = 0; jj < 8; jj++) {
                int od = lane4 * 2 + 8 * jj;
                float2 vv = *(const float2*)&Vs[kk * LDP + od];
                Oacc[2 * jj]     += pv * vv.x;
                Oacc[2 * jj + 1] += pv * vv.y;
            }
        }
    }

    float inv_l = 1.f / l_r;
    size_t orow = bh_off + (size_t)grow * E_DIM;
#pragma unroll
    for (int jj = 0; jj < 8; jj++) {
        int od = lane4 * 2 + 8 * jj;
        float2 val = make_float2(Oacc[2 * jj] * inv_l, Oacc[2 * jj + 1] * inv_l);
        *(float2*)&o[orow + od] = val;
    }
}

// ---------------------------------------------------------------------------
extern "C" void kernel_launch(void* const* d_in, const int* in_sizes, int n_in,
                              void* d_out, int out_size) {
    const float* x  = (const float*)d_in[0];
    const float* Wq = (const float*)d_in[1];
    const float* Wk = (const float*)d_in[2];
    const float* Wv = (const float*)d_in[3];
    const float* Wo = (const float*)d_in[4];
    float* out = (float*)d_out;

    float *qp, *kp, *vp, *ap;
    cudaGetSymbolAddress((void**)&qp, g_q);
    cudaGetSymbolAddress((void**)&kp, g_k);
    cudaGetSymbolAddress((void**)&vp, g_v);
    cudaGetSymbolAddress((void**)&ap, g_a);

    dim3 gg(E_DIM / 64, M_ROWS / 64);   // (16, 64)
    gemm_xwT<<<gg, 256>>>(x, Wq, qp);
    gemm_xwT<<<gg, 256>>>(x, Wk, kp);
    gemm_xwT<<<gg, 256>>>(x, Wv, vp);

    rope_kernel<<<(B_SZ * S_LEN * H_NUM * 32) / 256, 256>>>(qp, kp);

    cudaFuncSetAttribute(attn_kernel, cudaFuncAttributeMaxDynamicSharedMemorySize,
                         SMEM_ATTN);
    attn_kernel<<<dim3(S_LEN / 64, B_SZ * H_NUM), 256, SMEM_ATTN>>>(qp, kp, vp, ap);

    gemm_xwT<<<gg, 256>>>(ap, Wo, out);
}

// round 3
// speedup vs baseline: 1.4838x; 1.4838x over previous
#include <cuda_runtime.h>
#include <cuda_bf16.h>
#include <math.h>
#include <stdint.h>

// Problem constants
#define B_SZ 2
#define S_LEN 2048
#define E_DIM 1024
#define H_NUM 16
#define D_HEAD 64
#define M_ROWS (B_SZ * S_LEN)        // 4096
#define ATTN_SCALE 0.03125f          // 1/sqrt(1024)
#define GKP 3072                     // split K' = 3*1024
#define GK4 (GKP / 8)                // uint4 per row = 384

// ---------------- scratch (device globals: no allocation allowed) ----------
__device__ float g_q[M_ROWS * E_DIM];
__device__ float g_k[M_ROWS * E_DIM];
__device__ float g_v[M_ROWS * E_DIM];
__device__ float g_a[M_ROWS * E_DIM];
__device__ __nv_bfloat16 g_xhl[M_ROWS * GKP];      // x split  [hi|lo|hi]
__device__ __nv_bfloat16 g_ahl[M_ROWS * GKP];      // attn-out split
__device__ __nv_bfloat16 g_whl[4 * E_DIM * GKP];   // 4 weights [hi|hi|lo]
__device__ float2 g_tab[S_LEN * 32];               // rope cos/sin table

// ============================ PTX helpers (sm_80-era only) =================
__device__ __forceinline__ uint32_t smem_u32(const void* p) {
    uint32_t a;
    asm("{ .reg .u64 t; cvta.to.shared.u64 t, %1; cvt.u32.u64 %0, t; }"
        : "=r"(a) : "l"(p));
    return a;
}
#define CP_ASYNC16(dst, src) \
    asm volatile("cp.async.cg.shared.global [%0], [%1], 16;" \
                 :: "r"(dst), "l"(src))
#define CP_COMMIT() asm volatile("cp.async.commit_group;")
#define CP_WAIT(n)  asm volatile("cp.async.wait_group %0;" :: "n"(n))

__device__ __forceinline__ void ldm_x4(uint32_t* r, uint32_t addr) {
    asm volatile("ldmatrix.sync.aligned.x4.m8n8.shared.b16 {%0,%1,%2,%3}, [%4];"
                 : "=r"(r[0]), "=r"(r[1]), "=r"(r[2]), "=r"(r[3]) : "r"(addr));
}
__device__ __forceinline__ void mma16816(float* d, const uint32_t* a,
                                         const uint32_t* b) {
    asm volatile(
        "mma.sync.aligned.m16n8k16.row.col.f32.bf16.bf16.f32 "
        "{%0,%1,%2,%3}, {%4,%5,%6,%7}, {%8,%9}, {%0,%1,%2,%3};"
        : "+f"(d[0]), "+f"(d[1]), "+f"(d[2]), "+f"(d[3])
        : "r"(a[0]), "r"(a[1]), "r"(a[2]), "r"(a[3]), "r"(b[0]), "r"(b[1]));
}

// ============================ split converts ===============================
// out[r][seg*1024 + c] = (seg == lo_seg) ? bf16(a - bf16(a)) : bf16(a)
__global__ __launch_bounds__(256) void convert_split(const float* __restrict__ in,
                                                     __nv_bfloat16* __restrict__ out,
                                                     int lo_seg) {
    int idx = blockIdx.x * 256 + threadIdx.x;
    int r = idx >> 10, c = idx & 1023;
    float a = in[idx];
    __nv_bfloat16 hi = __float2bfloat16(a);
    __nv_bfloat16 lo = __float2bfloat16(a - __bfloat162float(hi));
    size_t base = (size_t)r * GKP + c;
    out[base]        = (lo_seg == 0) ? lo : hi;
    out[base + 1024] = (lo_seg == 1) ? lo : hi;
    out[base + 2048] = (lo_seg == 2) ? lo : hi;
}

// ============================ mma.sync GEMM ================================
// Y[M][1024] = A'[M][3072] x B'[1024][3072]^T  (bf16 in, fp32 out)
// 128x128 tile, BK=32, 8 warps of 32(M)x64(N), cp.async double buffer.
// smem pitch 80B (40 bf16) -> ldmatrix conflict-free.
#define GPITCH 80
#define STAGE_BYTES (2 * 128 * GPITCH)       // A tile + B tile = 20480
#define SMEM_B_REL (128 * GPITCH)            // 10240

__global__ __launch_bounds__(256, 2) void gemm_tc(const __nv_bfloat16* __restrict__ A,
                                                  const __nv_bfloat16* __restrict__ Bm,
                                                  float* __restrict__ Y) {
    __shared__ __align__(16) char smbuf[2 * STAGE_BYTES];   // 40 KB
    const uint32_t sb = smem_u32(smbuf);

    const int tid = threadIdx.x;
    const int wid = tid >> 5, lane = tid & 31;
    const int wm = wid & 3, wn = wid >> 2;
    const int mb = blockIdx.y * 128, nb = blockIdx.x * 128;

    // global load coords (4 x 16B per thread per chunk: 2 for A, 2 for B)
    const int lrow = tid >> 2;          // 0..63
    const int lkv = tid & 3;            // 0..3  (16B unit within 32-elt chunk? no: 4 units of 8 bf16)
    // each tile row needs 4 x uint4 (32 bf16); 128 rows * 4 = 512 loads; 256 thr -> 2 iters
    // iter it covers rows lrow + 64*it

    float acc[2][8][4];
#pragma unroll
    for (int i = 0; i < 2; i++)
#pragma unroll
        for (int j = 0; j < 8; j++)
#pragma unroll
            for (int q = 0; q < 4; q++) acc[i][j][q] = 0.f;

    const uint4* gA = (const uint4*)A;
    const uint4* gB = (const uint4*)Bm;

    // ---- async load of chunk c into stage s ----
    auto load_chunk = [&](int c, int s) {
        uint32_t sbase = sb + s * STAGE_BYTES;
#pragma unroll
        for (int it = 0; it < 2; it++) {
            int row = lrow + 64 * it;
            uint32_t so = sbase + row * GPITCH + lkv * 16;
            CP_ASYNC16(so, &gA[(size_t)(mb + row) * GK4 + c * 4 + lkv]);
            CP_ASYNC16(so + SMEM_B_REL, &gB[(size_t)(nb + row) * GK4 + c * 4 + lkv]);
        }
        CP_COMMIT();
    };

    load_chunk(0, 0);

    const int NCH = GKP / 32;   // 96
    for (int c = 0; c < NCH; c++) {
        if (c + 1 < NCH) {
            load_chunk(c + 1, (c + 1) & 1);
            CP_WAIT(1);
        } else {
            CP_WAIT(0);
        }
        __syncthreads();

        uint32_t abase = sb + (c & 1) * STAGE_BYTES + (wm * 32) * GPITCH;
        uint32_t bbase = sb + (c & 1) * STAGE_BYTES + SMEM_B_REL + (wn * 64) * GPITCH;

#pragma unroll
        for (int ks = 0; ks < 2; ks++) {
            uint32_t a_frag[2][4];
            uint32_t b_frag[8][2];
#pragma unroll
            for (int mi = 0; mi < 2; mi++) {
                uint32_t addr = abase + (mi * 16 + (lane & 15)) * GPITCH +
                                ks * 32 + (lane >> 4) * 16;
                ldm_x4(a_frag[mi], addr);
            }
#pragma unroll
            for (int bj = 0; bj < 4; bj++) {
                uint32_t r4[4];
                uint32_t addr = bbase +
                                (bj * 16 + (lane & 7) + ((lane >> 4) & 1) * 8) * GPITCH +
                                ks * 32 + ((lane >> 3) & 1) * 16;
                ldm_x4(r4, addr);
                b_frag[2 * bj][0] = r4[0]; b_frag[2 * bj][1] = r4[1];
                b_frag[2 * bj + 1][0] = r4[2]; b_frag[2 * bj + 1][1] = r4[3];
            }
#pragma unroll
            for (int mi = 0; mi < 2; mi++)
#pragma unroll
                for (int nj = 0; nj < 8; nj++)
                    mma16816(acc[mi][nj], a_frag[mi], b_frag[nj]);
        }
        __syncthreads();
    }

    // ---- store fp32 result ----
    const int tq = lane >> 2, tr = lane & 3;
#pragma unroll
    for (int mi = 0; mi < 2; mi++) {
#pragma unroll
        for (int half = 0; half < 2; half++) {
            int row = mb + wm * 32 + mi * 16 + tq + 8 * half;
            float* yr = &Y[(size_t)row * E_DIM + nb + wn * 64];
#pragma unroll
            for (int nj = 0; nj < 8; nj++) {
                float2 v = make_float2(acc[mi][nj][2 * half],
                                       acc[mi][nj][2 * half + 1]);
                *(float2*)&yr[nj * 8 + 2 * tr] = v;
            }
        }
    }
}

// ============================ RoPE =========================================
__global__ __launch_bounds__(256) void rope_table(float2* __restrict__ tab) {
    int idx = blockIdx.x * 256 + threadIdx.x;   // 65536
    int s = idx >> 5, i = idx & 31;
    double inv = exp(-((double)(2 * i) / 64.0) * log(10000.0));
    double cd, sd;
    sincos((double)s * inv, &sd, &cd);
    tab[idx] = make_float2((float)cd, (float)sd);
}

__global__ __launch_bounds__(256) void rope_apply(float* __restrict__ q,
                                                  float* __restrict__ k,
                                                  const float2* __restrict__ tab) {
    int p = blockIdx.x * 256 + threadIdx.x;     // 2M
    int i = p & 31;
    int h = (p >> 5) & 15;
    int s = (p >> 9) & 2047;
    int b = p >> 20;
    size_t off = ((size_t)(b * S_LEN + s) * E_DIM + h * D_HEAD + 2 * i);
    float2 cs = tab[s * 32 + i];
    float c = cs.x, sn = cs.y;

    float x1 = q[off], x2 = q[off + 1];
    q[off]     = x1 * c - x2 * sn;
    q[off + 1] = x2 * c + x1 * sn;
    x1 = k[off]; x2 = k[off + 1];
    k[off]     = x1 * c - x2 * sn;
    k[off + 1] = x2 * c + x1 * sn;
}

// ============================ flash attention (fp32) =======================
#define LDP 66
#define SMEM_ATTN (4 * 64 * LDP * 4)

__global__ __launch_bounds__(256) void attn_kernel(const float* __restrict__ q,
                                                   const float* __restrict__ k,
                                                   const float* __restrict__ v,
                                                   float* __restrict__ o) {
    extern __shared__ float smf[];
    float* Qs = smf;
    float* Ks = Qs + 64 * LDP;
    float* Vs = Ks + 64 * LDP;
    float* Ps = Vs + 64 * LDP;

    int tid = threadIdx.x;
    int bh = blockIdx.y;
    int b = bh >> 4;
    int h = bh & 15;
    int qbase = blockIdx.x * 64;
    const size_t bh_off = (size_t)b * S_LEN * E_DIM + (size_t)h * D_HEAD;

    for (int idx = tid; idx < 64 * 32; idx += 256) {
        int rr = idx >> 5;
        int d2 = idx & 31;
        float2 val = *(const float2*)&q[bh_off + (size_t)(qbase + rr) * E_DIM + 2 * d2];
        Qs[rr * LDP + 2 * d2]     = val.x;
        Qs[rr * LDP + 2 * d2 + 1] = val.y;
    }

    int r = tid >> 2;
    int lane4 = tid & 3;

    float m_r = -INFINITY;
    float l_r = 0.f;
    float Oacc[16];
#pragma unroll
    for (int j = 0; j < 16; j++) Oacc[j] = 0.f;

    int grow = qbase + r;
    int ktiles = blockIdx.x + 1;

    for (int kt = 0; kt < ktiles; kt++) {
        int kbase = kt * 64;
        __syncthreads();
        for (int idx = tid; idx < 64 * 32; idx += 256) {
            int rr = idx >> 5;
            int d2 = idx & 31;
            size_t gofs = bh_off + (size_t)(kbase + rr) * E_DIM + 2 * d2;
            float2 kv = *(const float2*)&k[gofs];
            float2 vv = *(const float2*)&v[gofs];
            Ks[rr * LDP + 2 * d2]     = kv.x;
            Ks[rr * LDP + 2 * d2 + 1] = kv.y;
            Vs[rr * LDP + 2 * d2]     = vv.x;
            Vs[rr * LDP + 2 * d2 + 1] = vv.y;
        }
        __syncthreads();

        float acc[16];
#pragma unroll
        for (int j = 0; j < 16; j++) acc[j] = 0.f;

        for (int d2 = 0; d2 < 32; d2++) {
            float2 qv = *(const float2*)&Qs[r * LDP + 2 * d2];
#pragma unroll
            for (int j = 0; j < 16; j++) {
                int c = lane4 + 4 * j;
                float2 kv = *(const float2*)&Ks[c * LDP + 2 * d2];
                acc[j] += qv.x * kv.x + qv.y * kv.y;
            }
        }

        bool diag = (kt == blockIdx.x);
        float tmax = -INFINITY;
#pragma unroll
        for (int j = 0; j < 16; j++) {
            float sc = acc[j] * ATTN_SCALE;
            if (diag && (kbase + lane4 + 4 * j) > grow) sc = -INFINITY;
            acc[j] = sc;
            tmax = fmaxf(tmax, sc);
        }
        tmax = fmaxf(tmax, __shfl_xor_sync(0xFFFFFFFF, tmax, 1));
        tmax = fmaxf(tmax, __shfl_xor_sync(0xFFFFFFFF, tmax, 2));

        float m_new = fmaxf(m_r, tmax);
        float alpha = __expf(m_r - m_new);

        float psum = 0.f;
#pragma unroll
        for (int j = 0; j < 16; j++) {
            float pv = __expf(acc[j] - m_new);
            Ps[r * LDP + lane4 + 4 * j] = pv;
            psum += pv;
        }
        psum += __shfl_xor_sync(0xFFFFFFFF, psum, 1);
        psum += __shfl_xor_sync(0xFFFFFFFF, psum, 2);

        l_r = l_r * alpha + psum;
        m_r = m_new;
#pragma unroll
        for (int j = 0; j < 16; j++) Oacc[j] *= alpha;

        __syncthreads();

        for (int kk = 0; kk < 64; kk++) {
            float pv = Ps[r * LDP + kk];
#pragma unroll
            for (int jj = 0; jj < 8; jj++) {
                int od = lane4 * 2 + 8 * jj;
                float2 vv = *(const float2*)&Vs[kk * LDP + od];
                Oacc[2 * jj]     += pv * vv.x;
                Oacc[2 * jj + 1] += pv * vv.y;
            }
        }
    }

    float inv_l = 1.f / l_r;
    size_t orow = bh_off + (size_t)grow * E_DIM;
#pragma unroll
    for (int jj = 0; jj < 8; jj++) {
        int od = lane4 * 2 + 8 * jj;
        float2 val = make_float2(Oacc[2 * jj] * inv_l, Oacc[2 * jj + 1] * inv_l);
        *(float2*)&o[orow + od] = val;
    }
}

// ============================ launch =======================================
extern "C" void kernel_launch(void* const* d_in, const int* in_sizes, int n_in,
                              void* d_out, int out_size) {
    const float* x  = (const float*)d_in[0];
    const float* Wq = (const float*)d_in[1];
    const float* Wk = (const float*)d_in[2];
    const float* Wv = (const float*)d_in[3];
    const float* Wo = (const float*)d_in[4];
    float* out = (float*)d_out;

    float *qp, *kp, *vp, *ap;
    __nv_bfloat16 *xhl, *ahl, *whl;
    float2* tab;
    cudaGetSymbolAddress((void**)&qp, g_q);
    cudaGetSymbolAddress((void**)&kp, g_k);
    cudaGetSymbolAddress((void**)&vp, g_v);
    cudaGetSymbolAddress((void**)&ap, g_a);
    cudaGetSymbolAddress((void**)&xhl, g_xhl);
    cudaGetSymbolAddress((void**)&ahl, g_ahl);
    cudaGetSymbolAddress((void**)&whl, g_whl);
    cudaGetSymbolAddress((void**)&tab, g_tab);

    rope_table<<<S_LEN * 32 / 256, 256>>>(tab);
    convert_split<<<M_ROWS * E_DIM / 256, 256>>>(x, xhl, 1);
    convert_split<<<E_DIM * E_DIM / 256, 256>>>(Wq, whl + 0 * (size_t)E_DIM * GKP, 2);
    convert_split<<<E_DIM * E_DIM / 256, 256>>>(Wk, whl + 1 * (size_t)E_DIM * GKP, 2);
    convert_split<<<E_DIM * E_DIM / 256, 256>>>(Wv, whl + 2 * (size_t)E_DIM * GKP, 2);
    convert_split<<<E_DIM * E_DIM / 256, 256>>>(Wo, whl + 3 * (size_t)E_DIM * GKP, 2);

    dim3 gg(E_DIM / 128, M_ROWS / 128);   // (8, 32)
    gemm_tc<<<gg, 256>>>(xhl, whl + 0 * (size_t)E_DIM * GKP, qp);
    gemm_tc<<<gg, 256>>>(xhl, whl + 1 * (size_t)E_DIM * GKP, kp);
    gemm_tc<<<gg, 256>>>(xhl, whl + 2 * (size_t)E_DIM * GKP, vp);

    rope_apply<<<(B_SZ * S_LEN * H_NUM * 32) / 256, 256>>>(qp, kp, tab);

    cudaFuncSetAttribute(attn_kernel, cudaFuncAttributeMaxDynamicSharedMemorySize,
                         SMEM_ATTN);
    attn_kernel<<<dim3(S_LEN / 64, B_SZ * H_NUM), 256, SMEM_ATTN>>>(qp, kp, vp, ap);

    convert_split<<<M_ROWS * E_DIM / 256, 256>>>(ap, ahl, 1);
    gemm_tc<<<gg, 256>>>(ahl, whl + 3 * (size_t)E_DIM * GKP, out);
}

// round 4
// speedup vs baseline: 6.0679x; 4.0894x over previous
#include <cuda_runtime.h>
#include <cuda_bf16.h>
#include <cuda_fp16.h>
#include <math.h>
#include <stdint.h>

// Problem constants
#define B_SZ 2
#define S_LEN 2048
#define E_DIM 1024
#define H_NUM 16
#define D_HEAD 64
#define M_ROWS (B_SZ * S_LEN)        // 4096
#define ATTN_SCALE 0.03125f          // 1/sqrt(1024)
#define GKP 3072                     // split K' = 3*1024

// ---------------- scratch (device globals: no allocation allowed) ----------
__device__ float g_q[M_ROWS * E_DIM];
__device__ float g_k[M_ROWS * E_DIM];
__device__ float g_v[M_ROWS * E_DIM];
__device__ float g_a[M_ROWS * E_DIM];
__device__ __half g_x16[M_ROWS * E_DIM];
__device__ __half g_wq16[E_DIM * E_DIM];
__device__ __half g_wk16[E_DIM * E_DIM];
__device__ __half g_q16[M_ROWS * E_DIM];
__device__ __half g_k16[M_ROWS * E_DIM];
__device__ __half g_v16[M_ROWS * E_DIM];
__device__ __nv_bfloat16 g_xhl[M_ROWS * GKP];      // x split  [hi|lo|hi]
__device__ __nv_bfloat16 g_ahl[M_ROWS * GKP];      // attn-out split
__device__ __nv_bfloat16 g_whl[2 * E_DIM * GKP];   // Wv, Wo splits [hi|hi|lo]
__device__ float2 g_tab[S_LEN * 32];               // rope cos/sin table

// ============================ PTX helpers (sm_80-era only) =================
__device__ __forceinline__ uint32_t smem_u32(const void* p) {
    uint32_t a;
    asm("{ .reg .u64 t; cvta.to.shared.u64 t, %1; cvt.u32.u64 %0, t; }"
        : "=r"(a) : "l"(p));
    return a;
}
#define CP_ASYNC16(dst, src) \
    asm volatile("cp.async.cg.shared.global [%0], [%1], 16;" \
                 :: "r"(dst), "l"(src))
#define CP_COMMIT() asm volatile("cp.async.commit_group;")
#define CP_WAIT(n)  asm volatile("cp.async.wait_group %0;" :: "n"(n))

__device__ __forceinline__ void ldm_x4(uint32_t* r, uint32_t addr) {
    asm volatile("ldmatrix.sync.aligned.x4.m8n8.shared.b16 {%0,%1,%2,%3}, [%4];"
                 : "=r"(r[0]), "=r"(r[1]), "=r"(r[2]), "=r"(r[3]) : "r"(addr));
}
__device__ __forceinline__ void ldm_x4_t(uint32_t* r, uint32_t addr) {
    asm volatile("ldmatrix.sync.aligned.x4.m8n8.trans.shared.b16 {%0,%1,%2,%3}, [%4];"
                 : "=r"(r[0]), "=r"(r[1]), "=r"(r[2]), "=r"(r[3]) : "r"(addr));
}
__device__ __forceinline__ void mma_bf16(float* d, const uint32_t* a,
                                         const uint32_t* b) {
    asm volatile(
        "mma.sync.aligned.m16n8k16.row.col.f32.bf16.bf16.f32 "
        "{%0,%1,%2,%3}, {%4,%5,%6,%7}, {%8,%9}, {%0,%1,%2,%3};"
        : "+f"(d[0]), "+f"(d[1]), "+f"(d[2]), "+f"(d[3])
        : "r"(a[0]), "r"(a[1]), "r"(a[2]), "r"(a[3]), "r"(b[0]), "r"(b[1]));
}
__device__ __forceinline__ void mma_f16(float* d, const uint32_t* a,
                                        const uint32_t* b) {
    asm volatile(
        "mma.sync.aligned.m16n8k16.row.col.f32.f16.f16.f32 "
        "{%0,%1,%2,%3}, {%4,%5,%6,%7}, {%8,%9}, {%0,%1,%2,%3};"
        : "+f"(d[0]), "+f"(d[1]), "+f"(d[2]), "+f"(d[3])
        : "r"(a[0]), "r"(a[1]), "r"(a[2]), "r"(a[3]), "r"(b[0]), "r"(b[1]));
}
__device__ __forceinline__ uint32_t f22h(float a, float b) {
    __half2 h = __floats2half2_rn(a, b);
    return *(uint32_t*)&h;
}

// ============================ converts =====================================
__global__ __launch_bounds__(256) void convert_f16(const float* __restrict__ in,
                                                   __half* __restrict__ out) {
    int idx = blockIdx.x * 256 + threadIdx.x;
    out[idx] = __float2half_rn(in[idx]);
}

// out[r][seg*1024 + c] = (seg == lo_seg) ? bf16(a - bf16(a)) : bf16(a)
__global__ __launch_bounds__(256) void convert_split(const float* __restrict__ in,
                                                     __nv_bfloat16* __restrict__ out,
                                                     int lo_seg) {
    int idx = blockIdx.x * 256 + threadIdx.x;
    int r = idx >> 10, c = idx & 1023;
    float a = in[idx];
    __nv_bfloat16 hi = __float2bfloat16(a);
    __nv_bfloat16 lo = __float2bfloat16(a - __bfloat162float(hi));
    size_t base = (size_t)r * GKP + c;
    out[base]        = (lo_seg == 0) ? lo : hi;
    out[base + 1024] = (lo_seg == 1) ? lo : hi;
    out[base + 2048] = (lo_seg == 2) ? lo : hi;
}

// ============================ mma.sync GEMM ================================
// Y[M][1024] = A[M][K] x B[1024][K]^T  (f16/bf16 in, fp32 out)
// 128x128 tile, BK=32, 8 warps of 32(M)x64(N), cp.async double buffer.
#define GPITCH 80
#define STAGE_BYTES (2 * 128 * GPITCH)       // 20480
#define SMEM_B_REL (128 * GPITCH)            // 10240

template <int K4, bool BF16>
__global__ __launch_bounds__(256, 2) void gemm_mma(const void* __restrict__ Av,
                                                   const void* __restrict__ Bv,
                                                   float* __restrict__ Y) {
    __shared__ __align__(16) char smbuf[2 * STAGE_BYTES];   // 40 KB
    const uint32_t sb = smem_u32(smbuf);

    const int tid = threadIdx.x;
    const int wid = tid >> 5, lane = tid & 31;
    const int wm = wid & 3, wn = wid >> 2;
    const int mb = blockIdx.y * 128, nb = blockIdx.x * 128;

    const int lrow = tid >> 2;
    const int lkv = tid & 3;

    float acc[2][8][4];
#pragma unroll
    for (int i = 0; i < 2; i++)
#pragma unroll
        for (int j = 0; j < 8; j++)
#pragma unroll
            for (int q = 0; q < 4; q++) acc[i][j][q] = 0.f;

    const uint4* gA = (const uint4*)Av;
    const uint4* gB = (const uint4*)Bv;

    auto load_chunk = [&](int c, int s) {
        uint32_t sbase = sb + s * STAGE_BYTES;
#pragma unroll
        for (int it = 0; it < 2; it++) {
            int row = lrow + 64 * it;
            uint32_t so = sbase + row * GPITCH + lkv * 16;
            CP_ASYNC16(so, &gA[(size_t)(mb + row) * K4 + c * 4 + lkv]);
            CP_ASYNC16(so + SMEM_B_REL, &gB[(size_t)(nb + row) * K4 + c * 4 + lkv]);
        }
        CP_COMMIT();
    };

    load_chunk(0, 0);

    const int NCH = K4 / 4;
    for (int c = 0; c < NCH; c++) {
        if (c + 1 < NCH) {
            load_chunk(c + 1, (c + 1) & 1);
            CP_WAIT(1);
        } else {
            CP_WAIT(0);
        }
        __syncthreads();

        uint32_t abase = sb + (c & 1) * STAGE_BYTES + (wm * 32) * GPITCH;
        uint32_t bbase = sb + (c & 1) * STAGE_BYTES + SMEM_B_REL + (wn * 64) * GPITCH;

#pragma unroll
        for (int ks = 0; ks < 2; ks++) {
            uint32_t a_frag[2][4];
            uint32_t b_frag[8][2];
#pragma unroll
            for (int mi = 0; mi < 2; mi++) {
                uint32_t addr = abase + (mi * 16 + (lane & 15)) * GPITCH +
                                ks * 32 + (lane >> 4) * 16;
                ldm_x4(a_frag[mi], addr);
            }
#pragma unroll
            for (int bj = 0; bj < 4; bj++) {
                uint32_t r4[4];
                uint32_t addr = bbase +
                                (bj * 16 + (lane & 7) + ((lane >> 4) & 1) * 8) * GPITCH +
                                ks * 32 + ((lane >> 3) & 1) * 16;
                ldm_x4(r4, addr);
                b_frag[2 * bj][0] = r4[0]; b_frag[2 * bj][1] = r4[1];
                b_frag[2 * bj + 1][0] = r4[2]; b_frag[2 * bj + 1][1] = r4[3];
            }
#pragma unroll
            for (int mi = 0; mi < 2; mi++)
#pragma unroll
                for (int nj = 0; nj < 8; nj++) {
                    if (BF16) mma_bf16(acc[mi][nj], a_frag[mi], b_frag[nj]);
                    else      mma_f16(acc[mi][nj], a_frag[mi], b_frag[nj]);
                }
        }
        __syncthreads();
    }

    const int tq = lane >> 2, tr = lane & 3;
#pragma unroll
    for (int mi = 0; mi < 2; mi++) {
#pragma unroll
        for (int half = 0; half < 2; half++) {
            int row = mb + wm * 32 + mi * 16 + tq + 8 * half;
            float* yr = &Y[(size_t)row * E_DIM + nb + wn * 64];
#pragma unroll
            for (int nj = 0; nj < 8; nj++) {
                float2 v = make_float2(acc[mi][nj][2 * half],
                                       acc[mi][nj][2 * half + 1]);
                *(float2*)&yr[nj * 8 + 2 * tr] = v;
            }
        }
    }
}

// ============================ RoPE =========================================
__global__ __launch_bounds__(256) void rope_table(float2* __restrict__ tab) {
    int idx = blockIdx.x * 256 + threadIdx.x;   // 65536
    int s = idx >> 5, i = idx & 31;
    double inv = exp(-((double)(2 * i) / 64.0) * log(10000.0));
    double cd, sd;
    sincos((double)s * inv, &sd, &cd);
    tab[idx] = make_float2((float)cd, (float)sd);
}

__global__ __launch_bounds__(256) void rope_apply(float* __restrict__ q,
                                                  float* __restrict__ k,
                                                  const float2* __restrict__ tab) {
    int p = blockIdx.x * 256 + threadIdx.x;     // 2M
    int i = p & 31;
    int h = (p >> 5) & 15;
    int s = (p >> 9) & 2047;
    int b = p >> 20;
    size_t off = ((size_t)(b * S_LEN + s) * E_DIM + h * D_HEAD + 2 * i);
    float2 cs = tab[s * 32 + i];
    float c = cs.x, sn = cs.y;

    float x1 = q[off], x2 = q[off + 1];
    q[off]     = x1 * c - x2 * sn;
    q[off + 1] = x2 * c + x1 * sn;
    x1 = k[off]; x2 = k[off + 1];
    k[off]     = x1 * c - x2 * sn;
    k[off + 1] = x2 * c + x1 * sn;
}

// ============================ flash attention (fp16 HMMA) ==================
// CTA: 128 threads (4 warps), 64 Q rows (warp = 16 rows), K-tiles of 64.
// smem pitch 72 f16 (144B) -> ldmatrix conflict-free.
#define AP 144                       // pitch bytes
#define ATILE (64 * AP)              // 9216 bytes per tile

__global__ __launch_bounds__(128) void attn_f16(const __half* __restrict__ q,
                                                const __half* __restrict__ k,
                                                const __half* __restrict__ v,
                                                float* __restrict__ o) {
    __shared__ __align__(16) char smQ[ATILE];
    __shared__ __align__(16) char smK[2 * ATILE];
    __shared__ __align__(16) char smV[2 * ATILE];

    const int tid = threadIdx.x, lane = tid & 31, w = tid >> 5;
    const int bx = blockIdx.x;
    const int bh = blockIdx.y;
    const int b = bh >> 4, h = bh & 15;
    const int qbase = bx * 64;
    const size_t bh_off = (size_t)b * S_LEN * E_DIM + (size_t)h * D_HEAD;

    const uint32_t sQ = smem_u32(smQ);
    const uint32_t sK0 = smem_u32(smK);
    const uint32_t sV0 = smem_u32(smV);

    // prefetch Q tile
#pragma unroll
    for (int i = 0; i < 4; i++) {
        int idx = tid + i * 128;
        int rr = idx >> 3, ch = idx & 7;
        CP_ASYNC16(sQ + rr * AP + ch * 16,
                   (const char*)(q + bh_off + (size_t)(qbase + rr) * E_DIM + ch * 8));
    }
    CP_COMMIT();

    auto load_kv = [&](int kt) {
        int buf = kt & 1;
        uint32_t bK = sK0 + buf * ATILE, bV = sV0 + buf * ATILE;
        int kbase = kt * 64;
#pragma unroll
        for (int i = 0; i < 4; i++) {
            int idx = tid + i * 128;
            int rr = idx >> 3, ch = idx & 7;
            size_t go = bh_off + (size_t)(kbase + rr) * E_DIM + ch * 8;
            CP_ASYNC16(bK + rr * AP + ch * 16, (const char*)(k + go));
            CP_ASYNC16(bV + rr * AP + ch * 16, (const char*)(v + go));
        }
        CP_COMMIT();
    };
    load_kv(0);

    CP_WAIT(1);              // Q group done (KV0 may still be in flight)
    __syncthreads();

    // Q fragments held in registers for whole kernel
    uint32_t qf[4][4];
    {
        uint32_t a0 = sQ + (16 * w + (lane & 15)) * AP + (lane >> 4) * 16;
#pragma unroll
        for (int dd = 0; dd < 4; dd++) ldm_x4(qf[dd], a0 + dd * 32);
    }

    const int g = lane >> 2, tr = lane & 3;
    const int rg0 = qbase + 16 * w + g;
    const int rg1 = rg0 + 8;

    float m0 = -1e30f, m1 = -1e30f, l0 = 0.f, l1 = 0.f;
    float o_[8][4];
#pragma unroll
    for (int j = 0; j < 8; j++)
#pragma unroll
        for (int e = 0; e < 4; e++) o_[j][e] = 0.f;

    const int ntiles = bx + 1;
    for (int kt = 0; kt < ntiles; kt++) {
        if (kt + 1 < ntiles) { load_kv(kt + 1); CP_WAIT(1); }
        else CP_WAIT(0);
        __syncthreads();
        int buf = kt & 1;
        uint32_t bK = sK0 + buf * ATILE, bV = sV0 + buf * ATILE;

        // ---- S = Q K^T : c[nj] covers t-cols 8nj..8nj+7 ----
        float c[8][4];
#pragma unroll
        for (int j = 0; j < 8; j++)
#pragma unroll
            for (int e = 0; e < 4; e++) c[j][e] = 0.f;

#pragma unroll
        for (int dd = 0; dd < 4; dd++) {
#pragma unroll
            for (int tt = 0; tt < 4; tt++) {
                uint32_t rB[4];
                uint32_t addr = bK +
                    (tt * 16 + (lane & 7) + ((lane >> 4) & 1) * 8) * AP +
                    dd * 32 + ((lane >> 3) & 1) * 16;
                ldm_x4(rB, addr);
                mma_f16(c[2 * tt], qf[dd], rB);
                mma_f16(c[2 * tt + 1], qf[dd], rB + 2);
            }
        }

        // ---- scale + causal mask + row max ----
        const bool diag = (kt == bx);
        const int kbase = kt * 64;
        float tm0 = -1e30f, tm1 = -1e30f;
#pragma unroll
        for (int nj = 0; nj < 8; nj++) {
            int cg = kbase + 8 * nj + 2 * tr;
#pragma unroll
            for (int e = 0; e < 4; e++) c[nj][e] *= ATTN_SCALE;
            if (diag) {
                if (cg     > rg0) c[nj][0] = -1e30f;
                if (cg + 1 > rg0) c[nj][1] = -1e30f;
                if (cg     > rg1) c[nj][2] = -1e30f;
                if (cg + 1 > rg1) c[nj][3] = -1e30f;
            }
            tm0 = fmaxf(tm0, fmaxf(c[nj][0], c[nj][1]));
            tm1 = fmaxf(tm1, fmaxf(c[nj][2], c[nj][3]));
        }
        tm0 = fmaxf(tm0, __shfl_xor_sync(0xFFFFFFFF, tm0, 1));
        tm0 = fmaxf(tm0, __shfl_xor_sync(0xFFFFFFFF, tm0, 2));
        tm1 = fmaxf(tm1, __shfl_xor_sync(0xFFFFFFFF, tm1, 1));
        tm1 = fmaxf(tm1, __shfl_xor_sync(0xFFFFFFFF, tm1, 2));

        float mn0 = fmaxf(m0, tm0), mn1 = fmaxf(m1, tm1);
        float al0 = __expf(m0 - mn0), al1 = __expf(m1 - mn1);

        float s0 = 0.f, s1 = 0.f;
#pragma unroll
        for (int nj = 0; nj < 8; nj++) {
            c[nj][0] = __expf(c[nj][0] - mn0);
            c[nj][1] = __expf(c[nj][1] - mn0);
            c[nj][2] = __expf(c[nj][2] - mn1);
            c[nj][3] = __expf(c[nj][3] - mn1);
            s0 += c[nj][0] + c[nj][1];
            s1 += c[nj][2] + c[nj][3];
        }
        s0 += __shfl_xor_sync(0xFFFFFFFF, s0, 1);
        s0 += __shfl_xor_sync(0xFFFFFFFF, s0, 2);
        s1 += __shfl_xor_sync(0xFFFFFFFF, s1, 1);
        s1 += __shfl_xor_sync(0xFFFFFFFF, s1, 2);

        l0 = l0 * al0 + s0;
        l1 = l1 * al1 + s1;
        m0 = mn0; m1 = mn1;
#pragma unroll
        for (int dj = 0; dj < 8; dj++) {
            o_[dj][0] *= al0; o_[dj][1] *= al0;
            o_[dj][2] *= al1; o_[dj][3] *= al1;
        }

        // ---- P fragments (fp16) from C registers ----
        uint32_t pa[4][4];
#pragma unroll
        for (int tk = 0; tk < 4; tk++) {
            pa[tk][0] = f22h(c[2 * tk][0],     c[2 * tk][1]);
            pa[tk][1] = f22h(c[2 * tk][2],     c[2 * tk][3]);
            pa[tk][2] = f22h(c[2 * tk + 1][0], c[2 * tk + 1][1]);
            pa[tk][3] = f22h(c[2 * tk + 1][2], c[2 * tk + 1][3]);
        }

        // ---- O += P V ----
#pragma unroll
        for (int tk = 0; tk < 4; tk++) {
#pragma unroll
            for (int dc = 0; dc < 4; dc++) {
                uint32_t rV[4];
                uint32_t addr = bV +
                    (tk * 16 + (lane & 7) + ((lane >> 3) & 1) * 8) * AP +
                    dc * 32 + ((lane >> 4) & 1) * 16;
                ldm_x4_t(rV, addr);
                mma_f16(o_[2 * dc], pa[tk], rV);
                mma_f16(o_[2 * dc + 1], pa[tk], rV + 2);
            }
        }
        __syncthreads();
    }

    // ---- normalize + store fp32 ----
    float il0 = 1.f / l0, il1 = 1.f / l1;
#pragma unroll
    for (int dj = 0; dj < 8; dj++) {
        int d = 8 * dj + 2 * tr;
        *(float2*)&o[bh_off + (size_t)rg0 * E_DIM + d] =
            make_float2(o_[dj][0] * il0, o_[dj][1] * il0);
        *(float2*)&o[bh_off + (size_t)rg1 * E_DIM + d] =
            make_float2(o_[dj][2] * il1, o_[dj][3] * il1);
    }
}

// ============================ launch =======================================
extern "C" void kernel_launch(void* const* d_in, const int* in_sizes, int n_in,
                              void* d_out, int out_size) {
    const float* x  = (const float*)d_in[0];
    const float* Wq = (const float*)d_in[1];
    const float* Wk = (const float*)d_in[2];
    const float* Wv = (const float*)d_in[3];
    const float* Wo = (const float*)d_in[4];
    float* out = (float*)d_out;

    float *qp, *kp, *vp, *ap;
    __half *x16, *wq16, *wk16, *q16, *k16, *v16;
    __nv_bfloat16 *xhl, *ahl, *whl;
    float2* tab;
    cudaGetSymbolAddress((void**)&qp, g_q);
    cudaGetSymbolAddress((void**)&kp, g_k);
    cudaGetSymbolAddress((void**)&vp, g_v);
    cudaGetSymbolAddress((void**)&ap, g_a);
    cudaGetSymbolAddress((void**)&x16, g_x16);
    cudaGetSymbolAddress((void**)&wq16, g_wq16);
    cudaGetSymbolAddress((void**)&wk16, g_wk16);
    cudaGetSymbolAddress((void**)&q16, g_q16);
    cudaGetSymbolAddress((void**)&k16, g_k16);
    cudaGetSymbolAddress((void**)&v16, g_v16);
    cudaGetSymbolAddress((void**)&xhl, g_xhl);
    cudaGetSymbolAddress((void**)&ahl, g_ahl);
    cudaGetSymbolAddress((void**)&whl, g_whl);
    cudaGetSymbolAddress((void**)&tab, g_tab);

    const int NXE = M_ROWS * E_DIM;     // 4M
    const int NWE = E_DIM * E_DIM;      // 1M

    rope_table<<<S_LEN * 32 / 256, 256>>>(tab);
    convert_f16<<<NXE / 256, 256>>>(x, x16);
    convert_f16<<<NWE / 256, 256>>>(Wq, wq16);
    convert_f16<<<NWE / 256, 256>>>(Wk, wk16);
    convert_split<<<NXE / 256, 256>>>(x, xhl, 1);
    convert_split<<<NWE / 256, 256>>>(Wv, whl + 0 * (size_t)E_DIM * GKP, 2);
    convert_split<<<NWE / 256, 256>>>(Wo, whl + 1 * (size_t)E_DIM * GKP, 2);

    dim3 gg(E_DIM / 128, M_ROWS / 128);   // (8, 32)
    gemm_mma<128, false><<<gg, 256>>>(x16, wq16, qp);
    gemm_mma<128, false><<<gg, 256>>>(x16, wk16, kp);
    gemm_mma<384, true><<<gg, 256>>>(xhl, whl + 0 * (size_t)E_DIM * GKP, vp);

    rope_apply<<<(B_SZ * S_LEN * H_NUM * 32) / 256, 256>>>(qp, kp, tab);

    convert_f16<<<NXE / 256, 256>>>(qp, q16);
    convert_f16<<<NXE / 256, 256>>>(kp, k16);
    convert_f16<<<NXE / 256, 256>>>(vp, v16);

    attn_f16<<<dim3(S_LEN / 64, B_SZ * H_NUM), 128>>>(q16, k16, v16, ap);

    convert_split<<<NXE / 256, 256>>>(ap, ahl, 1);
    gemm_mma<384, true><<<gg, 256>>>(ahl, whl + 1 * (size_t)E_DIM * GKP, out);
}

// round 5
// speedup vs baseline: 10.2605x; 1.6909x over previous
#include <cuda_runtime.h>
#include <cuda_bf16.h>
#include <cuda_fp16.h>
#include <math.h>
#include <stdint.h>

// Problem constants
#define B_SZ 2
#define S_LEN 2048
#define E_DIM 1024
#define H_NUM 16
#define D_HEAD 64
#define M_ROWS (B_SZ * S_LEN)        // 4096
#define ATTN_SCALE 0.03125f          // 1/sqrt(1024)

// ---------------- scratch (device globals: no allocation allowed) ----------
__device__ __half g_x16[M_ROWS * E_DIM];
__device__ __half g_wq16[E_DIM * E_DIM];
__device__ __half g_wk16[E_DIM * E_DIM];
__device__ __half g_wv16[E_DIM * E_DIM];
__device__ __half g_wo16[E_DIM * E_DIM];
__device__ __half g_q16[M_ROWS * E_DIM];
__device__ __half g_k16[M_ROWS * E_DIM];
__device__ __half g_v16[M_ROWS * E_DIM];
__device__ __half g_a16[M_ROWS * E_DIM];
__device__ float2 g_tab[S_LEN * 32];               // rope cos/sin table

// ============================ PTX helpers (sm_80-era only) =================
__device__ __forceinline__ uint32_t smem_u32(const void* p) {
    uint32_t a;
    asm("{ .reg .u64 t; cvta.to.shared.u64 t, %1; cvt.u32.u64 %0, t; }"
        : "=r"(a) : "l"(p));
    return a;
}
#define CP_ASYNC16(dst, src) \
    asm volatile("cp.async.cg.shared.global [%0], [%1], 16;" \
                 :: "r"(dst), "l"(src))
#define CP_COMMIT() asm volatile("cp.async.commit_group;")
#define CP_WAIT(n)  asm volatile("cp.async.wait_group %0;" :: "n"(n))

__device__ __forceinline__ void ldm_x4(uint32_t* r, uint32_t addr) {
    asm volatile("ldmatrix.sync.aligned.x4.m8n8.shared.b16 {%0,%1,%2,%3}, [%4];"
                 : "=r"(r[0]), "=r"(r[1]), "=r"(r[2]), "=r"(r[3]) : "r"(addr));
}
__device__ __forceinline__ void ldm_x4_t(uint32_t* r, uint32_t addr) {
    asm volatile("ldmatrix.sync.aligned.x4.m8n8.trans.shared.b16 {%0,%1,%2,%3}, [%4];"
                 : "=r"(r[0]), "=r"(r[1]), "=r"(r[2]), "=r"(r[3]) : "r"(addr));
}
__device__ __forceinline__ void mma_f16(float* d, const uint32_t* a,
                                        const uint32_t* b) {
    asm volatile(
        "mma.sync.aligned.m16n8k16.row.col.f32.f16.f16.f32 "
        "{%0,%1,%2,%3}, {%4,%5,%6,%7}, {%8,%9}, {%0,%1,%2,%3};"
        : "+f"(d[0]), "+f"(d[1]), "+f"(d[2]), "+f"(d[3])
        : "r"(a[0]), "r"(a[1]), "r"(a[2]), "r"(a[3]), "r"(b[0]), "r"(b[1]));
}
__device__ __forceinline__ uint32_t f22h(float a, float b) {
    __half2 h = __floats2half2_rn(a, b);
    return *(uint32_t*)&h;
}

// ============================ vectorized convert ===========================
// 8 elements per thread: float4 x2 -> uint4 of 8 halves
__global__ __launch_bounds__(256) void convert_f16_vec(const float4* __restrict__ in,
                                                       uint4* __restrict__ out) {
    int idx = blockIdx.x * 256 + threadIdx.x;
    float4 a = in[2 * idx], b = in[2 * idx + 1];
    uint4 o;
    o.x = f22h(a.x, a.y);
    o.y = f22h(a.z, a.w);
    o.z = f22h(b.x, b.y);
    o.w = f22h(b.z, b.w);
    out[idx] = o;
}

// ============================ mma.sync GEMM ================================
// Y[M][1024] = A[M][1024](f16) x B[1024][1024](f16)^T
// 128x128 tile, BK=32, 8 warps of 32(M)x64(N), cp.async double buffer.
#define GPITCH 80
#define STAGE_BYTES (2 * 128 * GPITCH)       // 20480
#define SMEM_B_REL (128 * GPITCH)            // 10240
#define GK4 128                               // uint4 per row (K=1024)

template <bool HALF_OUT>
__global__ __launch_bounds__(256, 2) void gemm_mma(const void* __restrict__ Av,
                                                   const void* __restrict__ Bv,
                                                   void* __restrict__ Yv) {
    __shared__ __align__(16) char smbuf[2 * STAGE_BYTES];   // 40 KB
    const uint32_t sb = smem_u32(smbuf);

    const int tid = threadIdx.x;
    const int wid = tid >> 5, lane = tid & 31;
    const int wm = wid & 3, wn = wid >> 2;
    const int mb = blockIdx.y * 128, nb = blockIdx.x * 128;

    const int lrow = tid >> 2;
    const int lkv = tid & 3;

    float acc[2][8][4];
#pragma unroll
    for (int i = 0; i < 2; i++)
#pragma unroll
        for (int j = 0; j < 8; j++)
#pragma unroll
            for (int q = 0; q < 4; q++) acc[i][j][q] = 0.f;

    const uint4* gA = (const uint4*)Av;
    const uint4* gB = (const uint4*)Bv;

    auto load_chunk = [&](int c, int s) {
        uint32_t sbase = sb + s * STAGE_BYTES;
#pragma unroll
        for (int it = 0; it < 2; it++) {
            int row = lrow + 64 * it;
            uint32_t so = sbase + row * GPITCH + lkv * 16;
            CP_ASYNC16(so, &gA[(size_t)(mb + row) * GK4 + c * 4 + lkv]);
            CP_ASYNC16(so + SMEM_B_REL, &gB[(size_t)(nb + row) * GK4 + c * 4 + lkv]);
        }
        CP_COMMIT();
    };

    load_chunk(0, 0);

    const int NCH = GK4 / 4;   // 32
    for (int c = 0; c < NCH; c++) {
        if (c + 1 < NCH) {
            load_chunk(c + 1, (c + 1) & 1);
            CP_WAIT(1);
        } else {
            CP_WAIT(0);
        }
        __syncthreads();

        uint32_t abase = sb + (c & 1) * STAGE_BYTES + (wm * 32) * GPITCH;
        uint32_t bbase = sb + (c & 1) * STAGE_BYTES + SMEM_B_REL + (wn * 64) * GPITCH;

#pragma unroll
        for (int ks = 0; ks < 2; ks++) {
            uint32_t a_frag[2][4];
            uint32_t b_frag[8][2];
#pragma unroll
            for (int mi = 0; mi < 2; mi++) {
                uint32_t addr = abase + (mi * 16 + (lane & 15)) * GPITCH +
                                ks * 32 + (lane >> 4) * 16;
                ldm_x4(a_frag[mi], addr);
            }
#pragma unroll
            for (int bj = 0; bj < 4; bj++) {
                uint32_t r4[4];
                uint32_t addr = bbase +
                                (bj * 16 + (lane & 7) + ((lane >> 4) & 1) * 8) * GPITCH +
                                ks * 32 + ((lane >> 3) & 1) * 16;
                ldm_x4(r4, addr);
                b_frag[2 * bj][0] = r4[0]; b_frag[2 * bj][1] = r4[1];
                b_frag[2 * bj + 1][0] = r4[2]; b_frag[2 * bj + 1][1] = r4[3];
            }
#pragma unroll
            for (int mi = 0; mi < 2; mi++)
#pragma unroll
                for (int nj = 0; nj < 8; nj++)
                    mma_f16(acc[mi][nj], a_frag[mi], b_frag[nj]);
        }
        __syncthreads();
    }

    const int tq = lane >> 2, tr = lane & 3;
#pragma unroll
    for (int mi = 0; mi < 2; mi++) {
#pragma unroll
        for (int half = 0; half < 2; half++) {
            int row = mb + wm * 32 + mi * 16 + tq + 8 * half;
            int col = nb + wn * 64;
            if (HALF_OUT) {
                __half* yr = (__half*)Yv + (size_t)row * E_DIM + col;
#pragma unroll
                for (int nj = 0; nj < 8; nj++) {
                    uint32_t hv = f22h(acc[mi][nj][2 * half],
                                       acc[mi][nj][2 * half + 1]);
                    *(uint32_t*)&yr[nj * 8 + 2 * tr] = hv;
                }
            } else {
                float* yr = (float*)Yv + (size_t)row * E_DIM + col;
#pragma unroll
                for (int nj = 0; nj < 8; nj++) {
                    float2 v = make_float2(acc[mi][nj][2 * half],
                                           acc[mi][nj][2 * half + 1]);
                    *(float2*)&yr[nj * 8 + 2 * tr] = v;
                }
            }
        }
    }
}

// ============================ RoPE =========================================
__global__ __launch_bounds__(256) void rope_table(float2* __restrict__ tab) {
    int idx = blockIdx.x * 256 + threadIdx.x;   // 65536
    int s = idx >> 5, i = idx & 31;
    double inv = exp(-((double)(2 * i) / 64.0) * log(10000.0));
    double cd, sd;
    sincos((double)s * inv, &sd, &cd);
    tab[idx] = make_float2((float)cd, (float)sd);
}

__global__ __launch_bounds__(256) void rope_apply_f16(__half* __restrict__ q,
                                                      __half* __restrict__ k,
                                                      const float2* __restrict__ tab) {
    int p = blockIdx.x * 256 + threadIdx.x;     // 2M pairs
    int i = p & 31;
    int h = (p >> 5) & 15;
    int s = (p >> 9) & 2047;
    int b = p >> 20;
    size_t off = ((size_t)(b * S_LEN + s) * E_DIM + h * D_HEAD + 2 * i);
    float2 cs = tab[s * 32 + i];
    float c = cs.x, sn = cs.y;

    __half2* qp = (__half2*)(q + off);
    __half2* kp = (__half2*)(k + off);
    float2 qv = __half22float2(*qp);
    float2 kv = __half22float2(*kp);
    *qp = __floats2half2_rn(qv.x * c - qv.y * sn, qv.y * c + qv.x * sn);
    *kp = __floats2half2_rn(kv.x * c - kv.y * sn, kv.y * c + kv.x * sn);
}

// ============================ flash attention (fp16 HMMA) ==================
// CTA: 128 threads (4 warps), 64 Q rows (warp = 16 rows), K-tiles of 64.
#define AP 144                       // pitch bytes
#define ATILE (64 * AP)              // 9216 bytes per tile

__global__ __launch_bounds__(128) void attn_f16(const __half* __restrict__ q,
                                                const __half* __restrict__ k,
                                                const __half* __restrict__ v,
                                                __half* __restrict__ o) {
    __shared__ __align__(16) char smQ[ATILE];
    __shared__ __align__(16) char smK[2 * ATILE];
    __shared__ __align__(16) char smV[2 * ATILE];

    const int tid = threadIdx.x, lane = tid & 31, w = tid >> 5;
    const int bx = blockIdx.x;
    const int bh = blockIdx.y;
    const int b = bh >> 4, h = bh & 15;
    const int qbase = bx * 64;
    const size_t bh_off = (size_t)b * S_LEN * E_DIM + (size_t)h * D_HEAD;

    const uint32_t sQ = smem_u32(smQ);
    const uint32_t sK0 = smem_u32(smK);
    const uint32_t sV0 = smem_u32(smV);

#pragma unroll
    for (int i = 0; i < 4; i++) {
        int idx = tid + i * 128;
        int rr = idx >> 3, ch = idx & 7;
        CP_ASYNC16(sQ + rr * AP + ch * 16,
                   (const char*)(q + bh_off + (size_t)(qbase + rr) * E_DIM + ch * 8));
    }
    CP_COMMIT();

    auto load_kv = [&](int kt) {
        int buf = kt & 1;
        uint32_t bK = sK0 + buf * ATILE, bV = sV0 + buf * ATILE;
        int kbase = kt * 64;
#pragma unroll
        for (int i = 0; i < 4; i++) {
            int idx = tid + i * 128;
            int rr = idx >> 3, ch = idx & 7;
            size_t go = bh_off + (size_t)(kbase + rr) * E_DIM + ch * 8;
            CP_ASYNC16(bK + rr * AP + ch * 16, (const char*)(k + go));
            CP_ASYNC16(bV + rr * AP + ch * 16, (const char*)(v + go));
        }
        CP_COMMIT();
    };
    load_kv(0);

    CP_WAIT(1);
    __syncthreads();

    uint32_t qf[4][4];
    {
        uint32_t a0 = sQ + (16 * w + (lane & 15)) * AP + (lane >> 4) * 16;
#pragma unroll
        for (int dd = 0; dd < 4; dd++) ldm_x4(qf[dd], a0 + dd * 32);
    }

    const int g = lane >> 2, tr = lane & 3;
    const int rg0 = qbase + 16 * w + g;
    const int rg1 = rg0 + 8;

    float m0 = -1e30f, m1 = -1e30f, l0 = 0.f, l1 = 0.f;
    float o_[8][4];
#pragma unroll
    for (int j = 0; j < 8; j++)
#pragma unroll
        for (int e = 0; e < 4; e++) o_[j][e] = 0.f;

    const int ntiles = bx + 1;
    for (int kt = 0; kt < ntiles; kt++) {
        if (kt + 1 < ntiles) { load_kv(kt + 1); CP_WAIT(1); }
        else CP_WAIT(0);
        __syncthreads();
        int buf = kt & 1;
        uint32_t bK = sK0 + buf * ATILE, bV = sV0 + buf * ATILE;

        float c[8][4];
#pragma unroll
        for (int j = 0; j < 8; j++)
#pragma unroll
            for (int e = 0; e < 4; e++) c[j][e] = 0.f;

#pragma unroll
        for (int dd = 0; dd < 4; dd++) {
#pragma unroll
            for (int tt = 0; tt < 4; tt++) {
                uint32_t rB[4];
                uint32_t addr = bK +
                    (tt * 16 + (lane & 7) + ((lane >> 4) & 1) * 8) * AP +
                    dd * 32 + ((lane >> 3) & 1) * 16;
                ldm_x4(rB, addr);
                mma_f16(c[2 * tt], qf[dd], rB);
                mma_f16(c[2 * tt + 1], qf[dd], rB + 2);
            }
        }

        const bool diag = (kt == bx);
        const int kbase = kt * 64;
        float tm0 = -1e30f, tm1 = -1e30f;
#pragma unroll
        for (int nj = 0; nj < 8; nj++) {
            int cg = kbase + 8 * nj + 2 * tr;
#pragma unroll
            for (int e = 0; e < 4; e++) c[nj][e] *= ATTN_SCALE;
            if (diag) {
                if (cg     > rg0) c[nj][0] = -1e30f;
                if (cg + 1 > rg0) c[nj][1] = -1e30f;
                if (cg     > rg1) c[nj][2] = -1e30f;
                if (cg + 1 > rg1) c[nj][3] = -1e30f;
            }
            tm0 = fmaxf(tm0, fmaxf(c[nj][0], c[nj][1]));
            tm1 = fmaxf(tm1, fmaxf(c[nj][2], c[nj][3]));
        }
        tm0 = fmaxf(tm0, __shfl_xor_sync(0xFFFFFFFF, tm0, 1));
        tm0 = fmaxf(tm0, __shfl_xor_sync(0xFFFFFFFF, tm0, 2));
        tm1 = fmaxf(tm1, __shfl_xor_sync(0xFFFFFFFF, tm1, 1));
        tm1 = fmaxf(tm1, __shfl_xor_sync(0xFFFFFFFF, tm1, 2));

        float mn0 = fmaxf(m0, tm0), mn1 = fmaxf(m1, tm1);
        float al0 = __expf(m0 - mn0), al1 = __expf(m1 - mn1);

        float s0 = 0.f, s1 = 0.f;
#pragma unroll
        for (int nj = 0; nj < 8; nj++) {
            c[nj][0] = __expf(c[nj][0] - mn0);
            c[nj][1] = __expf(c[nj][1] - mn0);
            c[nj][2] = __expf(c[nj][2] - mn1);
            c[nj][3] = __expf(c[nj][3] - mn1);
            s0 += c[nj][0] + c[nj][1];
            s1 += c[nj][2] + c[nj][3];
        }
        s0 += __shfl_xor_sync(0xFFFFFFFF, s0, 1);
        s0 += __shfl_xor_sync(0xFFFFFFFF, s0, 2);
        s1 += __shfl_xor_sync(0xFFFFFFFF, s1, 1);
        s1 += __shfl_xor_sync(0xFFFFFFFF, s1, 2);

        l0 = l0 * al0 + s0;
        l1 = l1 * al1 + s1;
        m0 = mn0; m1 = mn1;
#pragma unroll
        for (int dj = 0; dj < 8; dj++) {
            o_[dj][0] *= al0; o_[dj][1] *= al0;
            o_[dj][2] *= al1; o_[dj][3] *= al1;
        }

        uint32_t pa[4][4];
#pragma unroll
        for (int tk = 0; tk < 4; tk++) {
            pa[tk][0] = f22h(c[2 * tk][0],     c[2 * tk][1]);
            pa[tk][1] = f22h(c[2 * tk][2],     c[2 * tk][3]);
            pa[tk][2] = f22h(c[2 * tk + 1][0], c[2 * tk + 1][1]);
            pa[tk][3] = f22h(c[2 * tk + 1][2], c[2 * tk + 1][3]);
        }

#pragma unroll
        for (int tk = 0; tk < 4; tk++) {
#pragma unroll
            for (int dc = 0; dc < 4; dc++) {
                uint32_t rV[4];
                uint32_t addr = bV +
                    (tk * 16 + (lane & 7) + ((lane >> 3) & 1) * 8) * AP +
                    dc * 32 + ((lane >> 4) & 1) * 16;
                ldm_x4_t(rV, addr);
                mma_f16(o_[2 * dc], pa[tk], rV);
                mma_f16(o_[2 * dc + 1], pa[tk], rV + 2);
            }
        }
        __syncthreads();
    }

    // ---- normalize + store f16 ----
    float il0 = 1.f / l0, il1 = 1.f / l1;
#pragma unroll
    for (int dj = 0; dj < 8; dj++) {
        int d = 8 * dj + 2 * tr;
        *(uint32_t*)&o[bh_off + (size_t)rg0 * E_DIM + d] =
            f22h(o_[dj][0] * il0, o_[dj][1] * il0);
        *(uint32_t*)&o[bh_off + (size_t)rg1 * E_DIM + d] =
            f22h(o_[dj][2] * il1, o_[dj][3] * il1);
    }
}

// ============================ launch =======================================
extern "C" void kernel_launch(void* const* d_in, const int* in_sizes, int n_in,
                              void* d_out, int out_size) {
    const float* x  = (const float*)d_in[0];
    const float* Wq = (const float*)d_in[1];
    const float* Wk = (const float*)d_in[2];
    const float* Wv = (const float*)d_in[3];
    const float* Wo = (const float*)d_in[4];
    float* out = (float*)d_out;

    __half *x16, *wq16, *wk16, *wv16, *wo16, *q16, *k16, *v16, *a16;
    float2* tab;
    cudaGetSymbolAddress((void**)&x16, g_x16);
    cudaGetSymbolAddress((void**)&wq16, g_wq16);
    cudaGetSymbolAddress((void**)&wk16, g_wk16);
    cudaGetSymbolAddress((void**)&wv16, g_wv16);
    cudaGetSymbolAddress((void**)&wo16, g_wo16);
    cudaGetSymbolAddress((void**)&q16, g_q16);
    cudaGetSymbolAddress((void**)&k16, g_k16);
    cudaGetSymbolAddress((void**)&v16, g_v16);
    cudaGetSymbolAddress((void**)&a16, g_a16);
    cudaGetSymbolAddress((void**)&tab, g_tab);

    const int NXE = M_ROWS * E_DIM;     // 4M
    const int NWE = E_DIM * E_DIM;      // 1M

    rope_table<<<S_LEN * 32 / 256, 256>>>(tab);
    convert_f16_vec<<<NXE / (256 * 8), 256>>>((const float4*)x, (uint4*)x16);
    convert_f16_vec<<<NWE / (256 * 8), 256>>>((const float4*)Wq, (uint4*)wq16);
    convert_f16_vec<<<NWE / (256 * 8), 256>>>((const float4*)Wk, (uint4*)wk16);
    convert_f16_vec<<<NWE / (256 * 8), 256>>>((const float4*)Wv, (uint4*)wv16);
    convert_f16_vec<<<NWE / (256 * 8), 256>>>((const float4*)Wo, (uint4*)wo16);

    dim3 gg(E_DIM / 128, M_ROWS / 128);   // (8, 32)
    gemm_mma<true><<<gg, 256>>>(x16, wq16, q16);
    gemm_mma<true><<<gg, 256>>>(x16, wk16, k16);
    gemm_mma<true><<<gg, 256>>>(x16, wv16, v16);

    rope_apply_f16<<<(B_SZ * S_LEN * H_NUM * 32) / 256, 256>>>(q16, k16, tab);

    attn_f16<<<dim3(S_LEN / 64, B_SZ * H_NUM), 128>>>(q16, k16, v16, a16);

    gemm_mma<false><<<gg, 256>>>(a16, wo16, out);
}

// round 6
// speedup vs baseline: 10.3442x; 1.0082x over previous
#include <cuda_runtime.h>
#include <cuda_bf16.h>
#include <cuda_fp16.h>
#include <math.h>
#include <stdint.h>

// Problem constants
#define B_SZ 2
#define S_LEN 2048
#define E_DIM 1024
#define H_NUM 16
#define D_HEAD 64
#define M_ROWS (B_SZ * S_LEN)        // 4096
#define ATTN_SCALE 0.03125f          // 1/sqrt(1024)
#define LOG2E 1.4426950408889634f
#define SCALE2 (ATTN_SCALE * LOG2E)  // base-2 softmax scale

// ---------------- scratch (device globals: no allocation allowed) ----------
__device__ __half g_x16[M_ROWS * E_DIM];
__device__ __half g_wq16[E_DIM * E_DIM];
__device__ __half g_wk16[E_DIM * E_DIM];
__device__ __half g_wv16[E_DIM * E_DIM];
__device__ __half g_wo16[E_DIM * E_DIM];
__device__ __half g_q16[M_ROWS * E_DIM];
__device__ __half g_k16[M_ROWS * E_DIM];
__device__ __half g_v16[M_ROWS * E_DIM];
__device__ __half g_a16[M_ROWS * E_DIM];
__device__ float2 g_tab[S_LEN * 32];               // rope cos/sin table

// ============================ PTX helpers (sm_80-era only) =================
__device__ __forceinline__ uint32_t smem_u32(const void* p) {
    uint32_t a;
    asm("{ .reg .u64 t; cvta.to.shared.u64 t, %1; cvt.u32.u64 %0, t; }"
        : "=r"(a) : "l"(p));
    return a;
}
#define CP_ASYNC16(dst, src) \
    asm volatile("cp.async.cg.shared.global [%0], [%1], 16;" \
                 :: "r"(dst), "l"(src))
#define CP_COMMIT() asm volatile("cp.async.commit_group;")
#define CP_WAIT(n)  asm volatile("cp.async.wait_group %0;" :: "n"(n))

__device__ __forceinline__ void ldm_x4(uint32_t* r, uint32_t addr) {
    asm volatile("ldmatrix.sync.aligned.x4.m8n8.shared.b16 {%0,%1,%2,%3}, [%4];"
                 : "=r"(r[0]), "=r"(r[1]), "=r"(r[2]), "=r"(r[3]) : "r"(addr));
}
__device__ __forceinline__ void ldm_x4_t(uint32_t* r, uint32_t addr) {
    asm volatile("ldmatrix.sync.aligned.x4.m8n8.trans.shared.b16 {%0,%1,%2,%3}, [%4];"
                 : "=r"(r[0]), "=r"(r[1]), "=r"(r[2]), "=r"(r[3]) : "r"(addr));
}
__device__ __forceinline__ void mma_f16(float* d, const uint32_t* a,
                                        const uint32_t* b) {
    asm volatile(
        "mma.sync.aligned.m16n8k16.row.col.f32.f16.f16.f32 "
        "{%0,%1,%2,%3}, {%4,%5,%6,%7}, {%8,%9}, {%0,%1,%2,%3};"
        : "+f"(d[0]), "+f"(d[1]), "+f"(d[2]), "+f"(d[3])
        : "r"(a[0]), "r"(a[1]), "r"(a[2]), "r"(a[3]), "r"(b[0]), "r"(b[1]));
}
__device__ __forceinline__ uint32_t f22h(float a, float b) {
    __half2 h = __floats2half2_rn(a, b);
    return *(uint32_t*)&h;
}

// ============================ converts =====================================
__global__ __launch_bounds__(256) void convert_f16_vec(const float4* __restrict__ in,
                                                       uint4* __restrict__ out) {
    int idx = blockIdx.x * 256 + threadIdx.x;
    float4 a = in[2 * idx], b = in[2 * idx + 1];
    uint4 o;
    o.x = f22h(a.x, a.y); o.y = f22h(a.z, a.w);
    o.z = f22h(b.x, b.y); o.w = f22h(b.z, b.w);
    out[idx] = o;
}

// all 4 weight matrices in one launch (1M elems each, 8 per thread)
__global__ __launch_bounds__(256) void convert_w_f16(
    const float4* __restrict__ wq, const float4* __restrict__ wk,
    const float4* __restrict__ wv, const float4* __restrict__ wo,
    uint4* __restrict__ oq, uint4* __restrict__ ok,
    uint4* __restrict__ ov, uint4* __restrict__ oo) {
    int idx = blockIdx.x * 256 + threadIdx.x;     // 4 * 131072
    int sel = idx >> 17;
    int j = idx & 131071;
    const float4* in = (sel == 0) ? wq : (sel == 1) ? wk : (sel == 2) ? wv : wo;
    uint4* out = (sel == 0) ? oq : (sel == 1) ? ok : (sel == 2) ? ov : oo;
    float4 a = in[2 * j], b = in[2 * j + 1];
    uint4 o;
    o.x = f22h(a.x, a.y); o.y = f22h(a.z, a.w);
    o.z = f22h(b.x, b.y); o.w = f22h(b.z, b.w);
    out[j] = o;
}

// ============================ RoPE table ===================================
__global__ __launch_bounds__(256) void rope_table(float2* __restrict__ tab) {
    int idx = blockIdx.x * 256 + threadIdx.x;   // 65536
    int s = idx >> 5, i = idx & 31;
    double inv = exp(-((double)(2 * i) / 64.0) * log(10000.0));
    double cd, sd;
    sincos((double)s * inv, &sd, &cd);
    tab[idx] = make_float2((float)cd, (float)sd);
}

// ============================ mma.sync GEMM ================================
// Y[M][1024] = A[M][1024](f16) x B[1024][1024](f16)^T
// 128x128 tile, BK=32, 8 warps of 32(M)x64(N), cp.async double buffer.
// MODE: 0 = f16 out, 1 = f16 out + fused RoPE, 2 = f32 out
#define GPITCH 80
#define STAGE_BYTES (2 * 128 * GPITCH)       // 20480
#define SMEM_B_REL (128 * GPITCH)            // 10240
#define GK4 128                               // uint4 per row (K=1024)

template <int MODE>
__global__ __launch_bounds__(256, 2) void gemm_mma(const void* __restrict__ Av,
                                                   const void* __restrict__ Bv,
                                                   void* __restrict__ Yv,
                                                   const float2* __restrict__ tab) {
    __shared__ __align__(16) char smbuf[2 * STAGE_BYTES];   // 40 KB
    const uint32_t sb = smem_u32(smbuf);

    const int tid = threadIdx.x;
    const int wid = tid >> 5, lane = tid & 31;
    const int wm = wid & 3, wn = wid >> 2;
    const int mb = blockIdx.y * 128, nb = blockIdx.x * 128;

    const int lrow = tid >> 2;
    const int lkv = tid & 3;

    float acc[2][8][4];
#pragma unroll
    for (int i = 0; i < 2; i++)
#pragma unroll
        for (int j = 0; j < 8; j++)
#pragma unroll
            for (int q = 0; q < 4; q++) acc[i][j][q] = 0.f;

    const uint4* gA = (const uint4*)Av;
    const uint4* gB = (const uint4*)Bv;

    auto load_chunk = [&](int c, int s) {
        uint32_t sbase = sb + s * STAGE_BYTES;
#pragma unroll
        for (int it = 0; it < 2; it++) {
            int row = lrow + 64 * it;
            uint32_t so = sbase + row * GPITCH + lkv * 16;
            CP_ASYNC16(so, &gA[(size_t)(mb + row) * GK4 + c * 4 + lkv]);
            CP_ASYNC16(so + SMEM_B_REL, &gB[(size_t)(nb + row) * GK4 + c * 4 + lkv]);
        }
        CP_COMMIT();
    };

    load_chunk(0, 0);

    const int NCH = GK4 / 4;   // 32
    for (int c = 0; c < NCH; c++) {
        if (c + 1 < NCH) {
            load_chunk(c + 1, (c + 1) & 1);
            CP_WAIT(1);
        } else {
            CP_WAIT(0);
        }
        __syncthreads();

        uint32_t abase = sb + (c & 1) * STAGE_BYTES + (wm * 32) * GPITCH;
        uint32_t bbase = sb + (c & 1) * STAGE_BYTES + SMEM_B_REL + (wn * 64) * GPITCH;

#pragma unroll
        for (int ks = 0; ks < 2; ks++) {
            uint32_t a_frag[2][4];
            uint32_t b_frag[8][2];
#pragma unroll
            for (int mi = 0; mi < 2; mi++) {
                uint32_t addr = abase + (mi * 16 + (lane & 15)) * GPITCH +
                                ks * 32 + (lane >> 4) * 16;
                ldm_x4(a_frag[mi], addr);
            }
#pragma unroll
            for (int bj = 0; bj < 4; bj++) {
                uint32_t r4[4];
                uint32_t addr = bbase +
                                (bj * 16 + (lane & 7) + ((lane >> 4) & 1) * 8) * GPITCH +
                                ks * 32 + ((lane >> 3) & 1) * 16;
                ldm_x4(r4, addr);
                b_frag[2 * bj][0] = r4[0]; b_frag[2 * bj][1] = r4[1];
                b_frag[2 * bj + 1][0] = r4[2]; b_frag[2 * bj + 1][1] = r4[3];
            }
#pragma unroll
            for (int mi = 0; mi < 2; mi++)
#pragma unroll
                for (int nj = 0; nj < 8; nj++)
                    mma_f16(acc[mi][nj], a_frag[mi], b_frag[nj]);
        }
        __syncthreads();
    }

    const int tq = lane >> 2, tr = lane & 3;
#pragma unroll
    for (int mi = 0; mi < 2; mi++) {
#pragma unroll
        for (int half = 0; half < 2; half++) {
            int row = mb + wm * 32 + mi * 16 + tq + 8 * half;
            int col0 = nb + wn * 64;
            if (MODE == 2) {
                float* yr = (float*)Yv + (size_t)row * E_DIM + col0;
#pragma unroll
                for (int nj = 0; nj < 8; nj++)
                    *(float2*)&yr[nj * 8 + 2 * tr] =
                        make_float2(acc[mi][nj][2 * half], acc[mi][nj][2 * half + 1]);
            } else {
                __half* yr = (__half*)Yv + (size_t)row * E_DIM + col0;
                int s = row & (S_LEN - 1);
#pragma unroll
                for (int nj = 0; nj < 8; nj++) {
                    float x1 = acc[mi][nj][2 * half];
                    float x2 = acc[mi][nj][2 * half + 1];
                    if (MODE == 1) {
                        int col = col0 + nj * 8 + 2 * tr;
                        float2 cs = tab[s * 32 + ((col >> 1) & 31)];
                        float o1 = x1 * cs.x - x2 * cs.y;
                        float o2 = x2 * cs.x + x1 * cs.y;
                        x1 = o1; x2 = o2;
                    }
                    *(uint32_t*)&yr[nj * 8 + 2 * tr] = f22h(x1, x2);
                }
            }
        }
    }
}

// ============================ flash attention (fp16 HMMA) ==================
// CTA: 256 threads (8 warps), 128 Q rows (warp = 16 rows), K-tiles of 64.
#define AP 144                       // pitch bytes
#define QTILE (128 * AP)             // 18432
#define KTILE (64 * AP)              // 9216
#define ASMEM (QTILE + 4 * KTILE)    // 55296

__global__ __launch_bounds__(256) void attn_f16(const __half* __restrict__ q,
                                                const __half* __restrict__ k,
                                                const __half* __restrict__ v,
                                                __half* __restrict__ o) {
    extern __shared__ __align__(16) char smA[];
    const uint32_t sQ = smem_u32(smA);
    const uint32_t sK0 = sQ + QTILE;
    const uint32_t sV0 = sQ + QTILE + 2 * KTILE;

    const int tid = threadIdx.x, lane = tid & 31, w = tid >> 5;
    const int bx = gridDim.x - 1 - blockIdx.x;     // heavy CTAs launch first
    const int bh = blockIdx.y;
    const int b = bh >> 4, h = bh & 15;
    const int qbase = bx * 128;
    const size_t bh_off = (size_t)b * S_LEN * E_DIM + (size_t)h * D_HEAD;

    // Q tile: 128 rows x 8 chunks = 1024 cp.async over 256 threads
#pragma unroll
    for (int i = 0; i < 4; i++) {
        int idx = tid + i * 256;
        int rr = idx >> 3, ch = idx & 7;
        CP_ASYNC16(sQ + rr * AP + ch * 16,
                   (const char*)(q + bh_off + (size_t)(qbase + rr) * E_DIM + ch * 8));
    }
    CP_COMMIT();

    auto load_kv = [&](int kt) {
        int buf = kt & 1;
        uint32_t bK = sK0 + buf * KTILE, bV = sV0 + buf * KTILE;
        int kbase = kt * 64;
#pragma unroll
        for (int i = 0; i < 2; i++) {
            int idx = tid + i * 256;
            int rr = idx >> 3, ch = idx & 7;
            size_t go = bh_off + (size_t)(kbase + rr) * E_DIM + ch * 8;
            CP_ASYNC16(bK + rr * AP + ch * 16, (const char*)(k + go));
            CP_ASYNC16(bV + rr * AP + ch * 16, (const char*)(v + go));
        }
        CP_COMMIT();
    };
    load_kv(0);

    CP_WAIT(1);
    __syncthreads();

    // Q fragments held in registers for whole kernel (rows 16w..16w+15)
    uint32_t qf[4][4];
    {
        uint32_t a0 = sQ + (16 * w + (lane & 15)) * AP + (lane >> 4) * 16;
#pragma unroll
        for (int dd = 0; dd < 4; dd++) ldm_x4(qf[dd], a0 + dd * 32);
    }

    const int g = lane >> 2, tr = lane & 3;
    const int rg0 = qbase + 16 * w + g;
    const int rg1 = rg0 + 8;

    float m0 = -1e30f, m1 = -1e30f, l0 = 0.f, l1 = 0.f;
    float o_[8][4];
#pragma unroll
    for (int j = 0; j < 8; j++)
#pragma unroll
        for (int e = 0; e < 4; e++) o_[j][e] = 0.f;

    const int ntiles = 2 * bx + 2;
    for (int kt = 0; kt < ntiles; kt++) {
        if (kt + 1 < ntiles) { load_kv(kt + 1); CP_WAIT(1); }
        else CP_WAIT(0);
        __syncthreads();
        int buf = kt & 1;
        uint32_t bK = sK0 + buf * KTILE, bV = sV0 + buf * KTILE;

        // ---- S = Q K^T ----
        float c[8][4];
#pragma unroll
        for (int j = 0; j < 8; j++)
#pragma unroll
            for (int e = 0; e < 4; e++) c[j][e] = 0.f;

#pragma unroll
        for (int dd = 0; dd < 4; dd++) {
#pragma unroll
            for (int tt = 0; tt < 4; tt++) {
                uint32_t rB[4];
                uint32_t addr = bK +
                    (tt * 16 + (lane & 7) + ((lane >> 4) & 1) * 8) * AP +
                    dd * 32 + ((lane >> 3) & 1) * 16;
                ldm_x4(rB, addr);
                mma_f16(c[2 * tt], qf[dd], rB);
                mma_f16(c[2 * tt + 1], qf[dd], rB + 2);
            }
        }

        // ---- scale (base-2) + causal mask + row max ----
        const bool diag = (kt >= 2 * bx);
        const int kbase = kt * 64;
        float tm0 = -1e30f, tm1 = -1e30f;
#pragma unroll
        for (int nj = 0; nj < 8; nj++) {
            int cg = kbase + 8 * nj + 2 * tr;
#pragma unroll
            for (int e = 0; e < 4; e++) c[nj][e] *= SCALE2;
            if (diag) {
                if (cg     > rg0) c[nj][0] = -1e30f;
                if (cg + 1 > rg0) c[nj][1] = -1e30f;
                if (cg     > rg1) c[nj][2] = -1e30f;
                if (cg + 1 > rg1) c[nj][3] = -1e30f;
            }
            tm0 = fmaxf(tm0, fmaxf(c[nj][0], c[nj][1]));
            tm1 = fmaxf(tm1, fmaxf(c[nj][2], c[nj][3]));
        }
        tm0 = fmaxf(tm0, __shfl_xor_sync(0xFFFFFFFF, tm0, 1));
        tm0 = fmaxf(tm0, __shfl_xor_sync(0xFFFFFFFF, tm0, 2));
        tm1 = fmaxf(tm1, __shfl_xor_sync(0xFFFFFFFF, tm1, 1));
        tm1 = fmaxf(tm1, __shfl_xor_sync(0xFFFFFFFF, tm1, 2));

        float mn0 = fmaxf(m0, tm0), mn1 = fmaxf(m1, tm1);
        float al0 = exp2f(m0 - mn0), al1 = exp2f(m1 - mn1);

        float s0 = 0.f, s1 = 0.f;
#pragma unroll
        for (int nj = 0; nj < 8; nj++) {
            c[nj][0] = exp2f(c[nj][0] - mn0);
            c[nj][1] = exp2f(c[nj][1] - mn0);
            c[nj][2] = exp2f(c[nj][2] - mn1);
            c[nj][3] = exp2f(c[nj][3] - mn1);
            s0 += c[nj][0] + c[nj][1];
            s1 += c[nj][2] + c[nj][3];
        }
        s0 += __shfl_xor_sync(0xFFFFFFFF, s0, 1);
        s0 += __shfl_xor_sync(0xFFFFFFFF, s0, 2);
        s1 += __shfl_xor_sync(0xFFFFFFFF, s1, 1);
        s1 += __shfl_xor_sync(0xFFFFFFFF, s1, 2);

        l0 = l0 * al0 + s0;
        l1 = l1 * al1 + s1;
        m0 = mn0; m1 = mn1;
#pragma unroll
        for (int dj = 0; dj < 8; dj++) {
            o_[dj][0] *= al0; o_[dj][1] *= al0;
            o_[dj][2] *= al1; o_[dj][3] *= al1;
        }

        // ---- P fragments (fp16) ----
        uint32_t pa[4][4];
#pragma unroll
        for (int tk = 0; tk < 4; tk++) {
            pa[tk][0] = f22h(c[2 * tk][0],     c[2 * tk][1]);
            pa[tk][1] = f22h(c[2 * tk][2],     c[2 * tk][3]);
            pa[tk][2] = f22h(c[2 * tk + 1][0], c[2 * tk + 1][1]);
            pa[tk][3] = f22h(c[2 * tk + 1][2], c[2 * tk + 1][3]);
        }

        // ---- O += P V ----
#pragma unroll
        for (int tk = 0; tk < 4; tk++) {
#pragma unroll
            for (int dc = 0; dc < 4; dc++) {
                uint32_t rV[4];
                uint32_t addr = bV +
                    (tk * 16 + (lane & 7) + ((lane >> 3) & 1) * 8) * AP +
                    dc * 32 + ((lane >> 4) & 1) * 16;
                ldm_x4_t(rV, addr);
                mma_f16(o_[2 * dc], pa[tk], rV);
                mma_f16(o_[2 * dc + 1], pa[tk], rV + 2);
            }
        }
        __syncthreads();
    }

    // ---- normalize + store f16 ----
    float il0 = 1.f / l0, il1 = 1.f / l1;
#pragma unroll
    for (int dj = 0; dj < 8; dj++) {
        int d = 8 * dj + 2 * tr;
        *(uint32_t*)&o[bh_off + (size_t)rg0 * E_DIM + d] =
            f22h(o_[dj][0] * il0, o_[dj][1] * il0);
        *(uint32_t*)&o[bh_off + (size_t)rg1 * E_DIM + d] =
            f22h(o_[dj][2] * il1, o_[dj][3] * il1);
    }
}

// ============================ launch =======================================
extern "C" void kernel_launch(void* const* d_in, const int* in_sizes, int n_in,
                              void* d_out, int out_size) {
    const float* x  = (const float*)d_in[0];
    const float* Wq = (const float*)d_in[1];
    const float* Wk = (const float*)d_in[2];
    const float* Wv = (const float*)d_in[3];
    const float* Wo = (const float*)d_in[4];
    float* out = (float*)d_out;

    __half *x16, *wq16, *wk16, *wv16, *wo16, *q16, *k16, *v16, *a16;
    float2* tab;
    cudaGetSymbolAddress((void**)&x16, g_x16);
    cudaGetSymbolAddress((void**)&wq16, g_wq16);
    cudaGetSymbolAddress((void**)&wk16, g_wk16);
    cudaGetSymbolAddress((void**)&wv16, g_wv16);
    cudaGetSymbolAddress((void**)&wo16, g_wo16);
    cudaGetSymbolAddress((void**)&q16, g_q16);
    cudaGetSymbolAddress((void**)&k16, g_k16);
    cudaGetSymbolAddress((void**)&v16, g_v16);
    cudaGetSymbolAddress((void**)&a16, g_a16);
    cudaGetSymbolAddress((void**)&tab, g_tab);

    const int NXE = M_ROWS * E_DIM;     // 4M

    rope_table<<<S_LEN * 32 / 256, 256>>>(tab);
    convert_f16_vec<<<NXE / (256 * 8), 256>>>((const float4*)x, (uint4*)x16);
    convert_w_f16<<<2048, 256>>>((const float4*)Wq, (const float4*)Wk,
                                 (const float4*)Wv, (const float4*)Wo,
                                 (uint4*)wq16, (uint4*)wk16,
                                 (uint4*)wv16, (uint4*)wo16);

    dim3 gg(E_DIM / 128, M_ROWS / 128);   // (8, 32)
    gemm_mma<1><<<gg, 256>>>(x16, wq16, q16, tab);   // + fused RoPE
    gemm_mma<1><<<gg, 256>>>(x16, wk16, k16, tab);   // + fused RoPE
    gemm_mma<0><<<gg, 256>>>(x16, wv16, v16, nullptr);

    cudaFuncSetAttribute(attn_f16, cudaFuncAttributeMaxDynamicSharedMemorySize,
                         ASMEM);
    attn_f16<<<dim3(S_LEN / 128, B_SZ * H_NUM), 256, ASMEM>>>(q16, k16, v16, a16);

    gemm_mma<2><<<gg, 256>>>(a16, wo16, out, nullptr);
}

// round 7
// speedup vs baseline: 10.6918x; 1.0336x over previous
#include <cuda_runtime.h>
#include <cuda_bf16.h>
#include <cuda_fp16.h>
#include <math.h>
#include <stdint.h>

// Problem constants
#define B_SZ 2
#define S_LEN 2048
#define E_DIM 1024
#define H_NUM 16
#define D_HEAD 64
#define M_ROWS (B_SZ * S_LEN)        // 4096
#define ATTN_SCALE 0.03125f          // 1/sqrt(1024)
#define LOG2E 1.4426950408889634f
#define SCALE2 (ATTN_SCALE * LOG2E)  // base-2 softmax scale

// ---------------- scratch (device globals: no allocation allowed) ----------
__device__ __half g_x16[M_ROWS * E_DIM];
__device__ __half g_wq16[E_DIM * E_DIM];
__device__ __half g_wk16[E_DIM * E_DIM];
__device__ __half g_wv16[E_DIM * E_DIM];
__device__ __half g_wo16[E_DIM * E_DIM];
__device__ __half g_q16[M_ROWS * E_DIM];
__device__ __half g_k16[M_ROWS * E_DIM];
__device__ __half g_v16[M_ROWS * E_DIM];
__device__ __half g_a16[M_ROWS * E_DIM];
__device__ float2 g_tab[S_LEN * 32];               // rope cos/sin table

// ============================ PTX helpers (sm_80-era only) =================
__device__ __forceinline__ uint32_t smem_u32(const void* p) {
    uint32_t a;
    asm("{ .reg .u64 t; cvta.to.shared.u64 t, %1; cvt.u32.u64 %0, t; }"
        : "=r"(a) : "l"(p));
    return a;
}
#define CP_ASYNC16(dst, src) \
    asm volatile("cp.async.cg.shared.global [%0], [%1], 16;" \
                 :: "r"(dst), "l"(src))
#define CP_COMMIT() asm volatile("cp.async.commit_group;")
#define CP_WAIT(n)  asm volatile("cp.async.wait_group %0;" :: "n"(n))

__device__ __forceinline__ void ldm_x4(uint32_t* r, uint32_t addr) {
    asm volatile("ldmatrix.sync.aligned.x4.m8n8.shared.b16 {%0,%1,%2,%3}, [%4];"
                 : "=r"(r[0]), "=r"(r[1]), "=r"(r[2]), "=r"(r[3]) : "r"(addr));
}
__device__ __forceinline__ void ldm_x4_t(uint32_t* r, uint32_t addr) {
    asm volatile("ldmatrix.sync.aligned.x4.m8n8.trans.shared.b16 {%0,%1,%2,%3}, [%4];"
                 : "=r"(r[0]), "=r"(r[1]), "=r"(r[2]), "=r"(r[3]) : "r"(addr));
}
__device__ __forceinline__ void mma_f16(float* d, const uint32_t* a,
                                        const uint32_t* b) {
    asm volatile(
        "mma.sync.aligned.m16n8k16.row.col.f32.f16.f16.f32 "
        "{%0,%1,%2,%3}, {%4,%5,%6,%7}, {%8,%9}, {%0,%1,%2,%3};"
        : "+f"(d[0]), "+f"(d[1]), "+f"(d[2]), "+f"(d[3])
        : "r"(a[0]), "r"(a[1]), "r"(a[2]), "r"(a[3]), "r"(b[0]), "r"(b[1]));
}
__device__ __forceinline__ uint32_t f22h(float a, float b) {
    __half2 h = __floats2half2_rn(a, b);
    return *(uint32_t*)&h;
}

// ============================ converts =====================================
__global__ __launch_bounds__(256) void convert_f16_vec(const float4* __restrict__ in,
                                                       uint4* __restrict__ out) {
    int idx = blockIdx.x * 256 + threadIdx.x;
    float4 a = in[2 * idx], b = in[2 * idx + 1];
    uint4 o;
    o.x = f22h(a.x, a.y); o.y = f22h(a.z, a.w);
    o.z = f22h(b.x, b.y); o.w = f22h(b.z, b.w);
    out[idx] = o;
}

__global__ __launch_bounds__(256) void convert_w_f16(
    const float4* __restrict__ wq, const float4* __restrict__ wk,
    const float4* __restrict__ wv, const float4* __restrict__ wo,
    uint4* __restrict__ oq, uint4* __restrict__ ok,
    uint4* __restrict__ ov, uint4* __restrict__ oo) {
    int idx = blockIdx.x * 256 + threadIdx.x;     // 4 * 131072
    int sel = idx >> 17;
    int j = idx & 131071;
    const float4* in = (sel == 0) ? wq : (sel == 1) ? wk : (sel == 2) ? wv : wo;
    uint4* out = (sel == 0) ? oq : (sel == 1) ? ok : (sel == 2) ? ov : oo;
    float4 a = in[2 * j], b = in[2 * j + 1];
    uint4 o;
    o.x = f22h(a.x, a.y); o.y = f22h(a.z, a.w);
    o.z = f22h(b.x, b.y); o.w = f22h(b.z, b.w);
    out[j] = o;
}

// ============================ RoPE table ===================================
__global__ __launch_bounds__(256) void rope_table(float2* __restrict__ tab) {
    int idx = blockIdx.x * 256 + threadIdx.x;   // 65536
    int s = idx >> 5, i = idx & 31;
    double inv = exp(-((double)(2 * i) / 64.0) * log(10000.0));
    double cd, sd;
    sincos((double)s * inv, &sd, &cd);
    tab[idx] = make_float2((float)cd, (float)sd);
}

// ============================ mma.sync GEMM ================================
// Y[M][1024] = A[M][1024](f16) x B[1024][1024](f16)^T
// 128x128 tile, BK=32, 8 warps of 32(M)x64(N), 3-stage cp.async pipeline.
// MODE: 0 = f16 out, 1 = f16 out + fused RoPE, 2 = f32 out
#define GPITCH 80
#define STAGE_BYTES (2 * 128 * GPITCH)       // 20480
#define SMEM_B_REL (128 * GPITCH)            // 10240
#define GSMEM (3 * STAGE_BYTES)              // 61440
#define GK4 128                               // uint4 per row (K=1024)

template <int MODE>
__global__ __launch_bounds__(256, 2) void gemm_mma(const void* __restrict__ Av,
                                                   const void* __restrict__ Bv,
                                                   void* __restrict__ Yv,
                                                   const float2* __restrict__ tab) {
    extern __shared__ __align__(16) char smbuf[];
    const uint32_t sb = smem_u32(smbuf);

    const int tid = threadIdx.x;
    const int wid = tid >> 5, lane = tid & 31;
    const int wm = wid & 3, wn = wid >> 2;
    const int mb = blockIdx.y * 128, nb = blockIdx.x * 128;

    const int lrow = tid >> 2;
    const int lkv = tid & 3;

    float acc[2][8][4];
#pragma unroll
    for (int i = 0; i < 2; i++)
#pragma unroll
        for (int j = 0; j < 8; j++)
#pragma unroll
            for (int q = 0; q < 4; q++) acc[i][j][q] = 0.f;

    const uint4* gA = (const uint4*)Av;
    const uint4* gB = (const uint4*)Bv;

    auto load_chunk = [&](int c, int s) {
        uint32_t sbase = sb + s * STAGE_BYTES;
#pragma unroll
        for (int it = 0; it < 2; it++) {
            int row = lrow + 64 * it;
            uint32_t so = sbase + row * GPITCH + lkv * 16;
            CP_ASYNC16(so, &gA[(size_t)(mb + row) * GK4 + c * 4 + lkv]);
            CP_ASYNC16(so + SMEM_B_REL, &gB[(size_t)(nb + row) * GK4 + c * 4 + lkv]);
        }
        CP_COMMIT();
    };

    const int NCH = GK4 / 4;   // 32
    load_chunk(0, 0);
    load_chunk(1, 1);

    for (int c = 0; c < NCH; c++) {
        if (c < NCH - 1) CP_WAIT(1);
        else             CP_WAIT(0);
        __syncthreads();
        if (c + 2 < NCH) load_chunk(c + 2, (c + 2) % 3);

        uint32_t sbase = sb + (c % 3) * STAGE_BYTES;
        uint32_t abase = sbase + (wm * 32) * GPITCH;
        uint32_t bbase = sbase + SMEM_B_REL + (wn * 64) * GPITCH;

#pragma unroll
        for (int ks = 0; ks < 2; ks++) {
            uint32_t a_frag[2][4];
            uint32_t b_frag[8][2];
#pragma unroll
            for (int mi = 0; mi < 2; mi++) {
                uint32_t addr = abase + (mi * 16 + (lane & 15)) * GPITCH +
                                ks * 32 + (lane >> 4) * 16;
                ldm_x4(a_frag[mi], addr);
            }
#pragma unroll
            for (int bj = 0; bj < 4; bj++) {
                uint32_t r4[4];
                uint32_t addr = bbase +
                                (bj * 16 + (lane & 7) + ((lane >> 4) & 1) * 8) * GPITCH +
                                ks * 32 + ((lane >> 3) & 1) * 16;
                ldm_x4(r4, addr);
                b_frag[2 * bj][0] = r4[0]; b_frag[2 * bj][1] = r4[1];
                b_frag[2 * bj + 1][0] = r4[2]; b_frag[2 * bj + 1][1] = r4[3];
            }
#pragma unroll
            for (int mi = 0; mi < 2; mi++)
#pragma unroll
                for (int nj = 0; nj < 8; nj++)
                    mma_f16(acc[mi][nj], a_frag[mi], b_frag[nj]);
        }
    }

    const int tq = lane >> 2, tr = lane & 3;
#pragma unroll
    for (int mi = 0; mi < 2; mi++) {
#pragma unroll
        for (int half = 0; half < 2; half++) {
            int row = mb + wm * 32 + mi * 16 + tq + 8 * half;
            int col0 = nb + wn * 64;
            if (MODE == 2) {
                float* yr = (float*)Yv + (size_t)row * E_DIM + col0;
#pragma unroll
                for (int nj = 0; nj < 8; nj++)
                    *(float2*)&yr[nj * 8 + 2 * tr] =
                        make_float2(acc[mi][nj][2 * half], acc[mi][nj][2 * half + 1]);
            } else {
                __half* yr = (__half*)Yv + (size_t)row * E_DIM + col0;
                int s = row & (S_LEN - 1);
#pragma unroll
                for (int nj = 0; nj < 8; nj++) {
                    float x1 = acc[mi][nj][2 * half];
                    float x2 = acc[mi][nj][2 * half + 1];
                    if (MODE == 1) {
                        int col = col0 + nj * 8 + 2 * tr;
                        float2 cs = tab[s * 32 + ((col >> 1) & 31)];
                        float o1 = x1 * cs.x - x2 * cs.y;
                        float o2 = x2 * cs.x + x1 * cs.y;
                        x1 = o1; x2 = o2;
                    }
                    *(uint32_t*)&yr[nj * 8 + 2 * tr] = f22h(x1, x2);
                }
            }
        }
    }
}

// ============================ flash attention (fp16 HMMA) ==================
// CTA: 256 threads (8 warps), 128 Q rows (warp = 16 rows), K-tiles of 64,
// 3-stage K/V cp.async pipeline.
#define AP 144                       // pitch bytes
#define QTILE (128 * AP)             // 18432
#define KTILE (64 * AP)              // 9216
#define ASMEM (QTILE + 6 * KTILE)    // 73728

__global__ __launch_bounds__(256) void attn_f16(const __half* __restrict__ q,
                                                const __half* __restrict__ k,
                                                const __half* __restrict__ v,
                                                __half* __restrict__ o) {
    extern __shared__ __align__(16) char smA[];
    const uint32_t sQ = smem_u32(smA);
    const uint32_t sK0 = sQ + QTILE;
    const uint32_t sV0 = sQ + QTILE + 3 * KTILE;

    const int tid = threadIdx.x, lane = tid & 31, w = tid >> 5;
    const int bx = gridDim.x - 1 - blockIdx.x;     // heavy CTAs launch first
    const int bh = blockIdx.y;
    const int b = bh >> 4, h = bh & 15;
    const int qbase = bx * 128;
    const size_t bh_off = (size_t)b * S_LEN * E_DIM + (size_t)h * D_HEAD;

    // Q tile (group 0)
#pragma unroll
    for (int i = 0; i < 4; i++) {
        int idx = tid + i * 256;
        int rr = idx >> 3, ch = idx & 7;
        CP_ASYNC16(sQ + rr * AP + ch * 16,
                   (const char*)(q + bh_off + (size_t)(qbase + rr) * E_DIM + ch * 8));
    }
    CP_COMMIT();

    auto load_kv = [&](int kt) {
        int stage = kt % 3;
        uint32_t bK = sK0 + stage * KTILE, bV = sV0 + stage * KTILE;
        int kbase = kt * 64;
#pragma unroll
        for (int i = 0; i < 2; i++) {
            int idx = tid + i * 256;
            int rr = idx >> 3, ch = idx & 7;
            size_t go = bh_off + (size_t)(kbase + rr) * E_DIM + ch * 8;
            CP_ASYNC16(bK + rr * AP + ch * 16, (const char*)(k + go));
            CP_ASYNC16(bV + rr * AP + ch * 16, (const char*)(v + go));
        }
        CP_COMMIT();
    };
    const int ntiles = 2 * bx + 2;    // always >= 2
    load_kv(0);
    load_kv(1);

    CP_WAIT(2);                        // Q arrived (kv0, kv1 may be in flight)
    __syncthreads();

    // Q fragments held in registers for whole kernel (rows 16w..16w+15)
    uint32_t qf[4][4];
    {
        uint32_t a0 = sQ + (16 * w + (lane & 15)) * AP + (lane >> 4) * 16;
#pragma unroll
        for (int dd = 0; dd < 4; dd++) ldm_x4(qf[dd], a0 + dd * 32);
    }

    const int g = lane >> 2, tr = lane & 3;
    const int rg0 = qbase + 16 * w + g;
    const int rg1 = rg0 + 8;

    float m0 = -1e30f, m1 = -1e30f, l0 = 0.f, l1 = 0.f;
    float o_[8][4];
#pragma unroll
    for (int j = 0; j < 8; j++)
#pragma unroll
        for (int e = 0; e < 4; e++) o_[j][e] = 0.f;

    for (int kt = 0; kt < ntiles; kt++) {
        if (kt < ntiles - 1) CP_WAIT(1);
        else                 CP_WAIT(0);
        __syncthreads();
        if (kt + 2 < ntiles) load_kv(kt + 2);

        int stage = kt % 3;
        uint32_t bK = sK0 + stage * KTILE, bV = sV0 + stage * KTILE;

        // ---- S = Q K^T ----
        float c[8][4];
#pragma unroll
        for (int j = 0; j < 8; j++)
#pragma unroll
            for (int e = 0; e < 4; e++) c[j][e] = 0.f;

#pragma unroll
        for (int dd = 0; dd < 4; dd++) {
#pragma unroll
            for (int tt = 0; tt < 4; tt++) {
                uint32_t rB[4];
                uint32_t addr = bK +
                    (tt * 16 + (lane & 7) + ((lane >> 4) & 1) * 8) * AP +
                    dd * 32 + ((lane >> 3) & 1) * 16;
                ldm_x4(rB, addr);
                mma_f16(c[2 * tt], qf[dd], rB);
                mma_f16(c[2 * tt + 1], qf[dd], rB + 2);
            }
        }

        // ---- scale (base-2) + causal mask + row max ----
        const bool diag = (kt >= 2 * bx);
        const int kbase = kt * 64;
        float tm0 = -1e30f, tm1 = -1e30f;
#pragma unroll
        for (int nj = 0; nj < 8; nj++) {
            int cg = kbase + 8 * nj + 2 * tr;
#pragma unroll
            for (int e = 0; e < 4; e++) c[nj][e] *= SCALE2;
            if (diag) {
                if (cg     > rg0) c[nj][0] = -1e30f;
                if (cg + 1 > rg0) c[nj][1] = -1e30f;
                if (cg     > rg1) c[nj][2] = -1e30f;
                if (cg + 1 > rg1) c[nj][3] = -1e30f;
            }
            tm0 = fmaxf(tm0, fmaxf(c[nj][0], c[nj][1]));
            tm1 = fmaxf(tm1, fmaxf(c[nj][2], c[nj][3]));
        }
        tm0 = fmaxf(tm0, __shfl_xor_sync(0xFFFFFFFF, tm0, 1));
        tm0 = fmaxf(tm0, __shfl_xor_sync(0xFFFFFFFF, tm0, 2));
        tm1 = fmaxf(tm1, __shfl_xor_sync(0xFFFFFFFF, tm1, 1));
        tm1 = fmaxf(tm1, __shfl_xor_sync(0xFFFFFFFF, tm1, 2));

        float mn0 = fmaxf(m0, tm0), mn1 = fmaxf(m1, tm1);
        float al0 = exp2f(m0 - mn0), al1 = exp2f(m1 - mn1);

        float s0 = 0.f, s1 = 0.f;
#pragma unroll
        for (int nj = 0; nj < 8; nj++) {
            c[nj][0] = exp2f(c[nj][0] - mn0);
            c[nj][1] = exp2f(c[nj][1] - mn0);
            c[nj][2] = exp2f(c[nj][2] - mn1);
            c[nj][3] = exp2f(c[nj][3] - mn1);
            s0 += c[nj][0] + c[nj][1];
            s1 += c[nj][2] + c[nj][3];
        }
        s0 += __shfl_xor_sync(0xFFFFFFFF, s0, 1);
        s0 += __shfl_xor_sync(0xFFFFFFFF, s0, 2);
        s1 += __shfl_xor_sync(0xFFFFFFFF, s1, 1);
        s1 += __shfl_xor_sync(0xFFFFFFFF, s1, 2);

        l0 = l0 * al0 + s0;
        l1 = l1 * al1 + s1;
        m0 = mn0; m1 = mn1;
#pragma unroll
        for (int dj = 0; dj < 8; dj++) {
            o_[dj][0] *= al0; o_[dj][1] *= al0;
            o_[dj][2] *= al1; o_[dj][3] *= al1;
        }

        // ---- P fragments (fp16) ----
        uint32_t pa[4][4];
#pragma unroll
        for (int tk = 0; tk < 4; tk++) {
            pa[tk][0] = f22h(c[2 * tk][0],     c[2 * tk][1]);
            pa[tk][1] = f22h(c[2 * tk][2],     c[2 * tk][3]);
            pa[tk][2] = f22h(c[2 * tk + 1][0], c[2 * tk + 1][1]);
            pa[tk][3] = f22h(c[2 * tk + 1][2], c[2 * tk + 1][3]);
        }

        // ---- O += P V ----
#pragma unroll
        for (int tk = 0; tk < 4; tk++) {
#pragma unroll
            for (int dc = 0; dc < 4; dc++) {
                uint32_t rV[4];
                uint32_t addr = bV +
                    (tk * 16 + (lane & 7) + ((lane >> 3) & 1) * 8) * AP +
                    dc * 32 + ((lane >> 4) & 1) * 16;
                ldm_x4_t(rV, addr);
                mma_f16(o_[2 * dc], pa[tk], rV);
                mma_f16(o_[2 * dc + 1], pa[tk], rV + 2);
            }
        }
    }

    // ---- normalize + store f16 ----
    float il0 = 1.f / l0, il1 = 1.f / l1;
#pragma unroll
    for (int dj = 0; dj < 8; dj++) {
        int d = 8 * dj + 2 * tr;
        *(uint32_t*)&o[bh_off + (size_t)rg0 * E_DIM + d] =
            f22h(o_[dj][0] * il0, o_[dj][1] * il0);
        *(uint32_t*)&o[bh_off + (size_t)rg1 * E_DIM + d] =
            f22h(o_[dj][2] * il1, o_[dj][3] * il1);
    }
}

// ============================ launch =======================================
extern "C" void kernel_launch(void* const* d_in, const int* in_sizes, int n_in,
                              void* d_out, int out_size) {
    const float* x  = (const float*)d_in[0];
    const float* Wq = (const float*)d_in[1];
    const float* Wk = (const float*)d_in[2];
    const float* Wv = (const float*)d_in[3];
    const float* Wo = (const float*)d_in[4];
    float* out = (float*)d_out;

    __half *x16, *wq16, *wk16, *wv16, *wo16, *q16, *k16, *v16, *a16;
    float2* tab;
    cudaGetSymbolAddress((void**)&x16, g_x16);
    cudaGetSymbolAddress((void**)&wq16, g_wq16);
    cudaGetSymbolAddress((void**)&wk16, g_wk16);
    cudaGetSymbolAddress((void**)&wv16, g_wv16);
    cudaGetSymbolAddress((void**)&wo16, g_wo16);
    cudaGetSymbolAddress((void**)&q16, g_q16);
    cudaGetSymbolAddress((void**)&k16, g_k16);
    cudaGetSymbolAddress((void**)&v16, g_v16);
    cudaGetSymbolAddress((void**)&a16, g_a16);
    cudaGetSymbolAddress((void**)&tab, g_tab);

    const int NXE = M_ROWS * E_DIM;     // 4M

    cudaFuncSetAttribute(gemm_mma<0>, cudaFuncAttributeMaxDynamicSharedMemorySize, GSMEM);
    cudaFuncSetAttribute(gemm_mma<1>, cudaFuncAttributeMaxDynamicSharedMemorySize, GSMEM);
    cudaFuncSetAttribute(gemm_mma<2>, cudaFuncAttributeMaxDynamicSharedMemorySize, GSMEM);
    cudaFuncSetAttribute(attn_f16, cudaFuncAttributeMaxDynamicSharedMemorySize, ASMEM);

    rope_table<<<S_LEN * 32 / 256, 256>>>(tab);
    convert_f16_vec<<<NXE / (256 * 8), 256>>>((const float4*)x, (uint4*)x16);
    convert_w_f16<<<2048, 256>>>((const float4*)Wq, (const float4*)Wk,
                                 (const float4*)Wv, (const float4*)Wo,
                                 (uint4*)wq16, (uint4*)wk16,
                                 (uint4*)wv16, (uint4*)wo16);

    dim3 gg(E_DIM / 128, M_ROWS / 128);   // (8, 32)
    gemm_mma<1><<<gg, 256, GSMEM>>>(x16, wq16, q16, tab);   // + fused RoPE
    gemm_mma<1><<<gg, 256, GSMEM>>>(x16, wk16, k16, tab);   // + fused RoPE
    gemm_mma<0><<<gg, 256, GSMEM>>>(x16, wv16, v16, nullptr);

    attn_f16<<<dim3(S_LEN / 128, B_SZ * H_NUM), 256, ASMEM>>>(q16, k16, v16, a16);

    gemm_mma<2><<<gg, 256, GSMEM>>>(a16, wo16, out, nullptr);
}